// round 1
// baseline (speedup 1.0000x reference)
#include <cuda_runtime.h>

#define BB 4
#define LL 128
#define DM 256
#define VV 50257
#define DW 768
#define HH 8
#define EE 32
#define SPLITS 16
#define VT 32

// ---- scratch (static device allocations; no cudaMalloc anywhere) ----
__device__ float g_query[BB * LL * DM];                   // 512 x 256
__device__ float g_key[(size_t)VV * DM];                  // 50257 x 256
__device__ float g_value[(size_t)VV * DM];                // 50257 x 256
__device__ float g_part[BB * HH * SPLITS * LL * EE];      // split-K partials
__device__ float g_reprog[BB * LL * DM];                  // 512 x 256

// ============================================================
// Generic fp32 SGEMM: C[M,N] = A[M,K] @ B[K,N] + bias[N]
// 128x128 block tile, BK=16, 256 threads, 8x8 micro-tile.
// Requires K % 16 == 0, N % 128 == 0 (true for all uses here).
// M is bounds-checked.
// ============================================================
__global__ __launch_bounds__(256) void sgemm_bias(
    const float* __restrict__ A, const float* __restrict__ Bw,
    const float* __restrict__ bias, float* __restrict__ C,
    int M, int N, int K)
{
    __shared__ float As[16][132];   // transposed A tile: As[k][m]
    __shared__ float Bs[16][132];   // Bs[k][n]

    int t  = threadIdx.x;
    int tx = t & 15;
    int ty = t >> 4;
    int mBase = blockIdx.x * 128;
    int nBase = blockIdx.y * 128;

    float acc[8][8];
#pragma unroll
    for (int i = 0; i < 8; i++)
#pragma unroll
        for (int j = 0; j < 8; j++) acc[i][j] = 0.f;

    for (int k0 = 0; k0 < K; k0 += 16) {
        // --- load A tile: 128 rows x 16 cols = 512 float4, 2 per thread ---
#pragma unroll
        for (int r = 0; r < 2; r++) {
            int idx = t * 2 + r;
            int row = idx >> 2;            // 0..127
            int k4  = (idx & 3) * 4;       // 0,4,8,12
            float4 av;
            if (mBase + row < M)
                av = *(const float4*)(A + (size_t)(mBase + row) * K + k0 + k4);
            else
                av = make_float4(0.f, 0.f, 0.f, 0.f);
            As[k4 + 0][row] = av.x;
            As[k4 + 1][row] = av.y;
            As[k4 + 2][row] = av.z;
            As[k4 + 3][row] = av.w;
        }
        // --- load B tile: 16 rows x 128 cols = 512 float4, 2 per thread ---
#pragma unroll
        for (int r = 0; r < 2; r++) {
            int idx = t * 2 + r;
            int kr = idx >> 5;             // 0..15
            int c4 = (idx & 31) * 4;       // 0..124
            float4 bv = *(const float4*)(Bw + (size_t)(k0 + kr) * N + nBase + c4);
            *(float4*)&Bs[kr][c4] = bv;
        }
        __syncthreads();

#pragma unroll
        for (int kk = 0; kk < 16; kk++) {
            float4 a0 = *(const float4*)&As[kk][ty * 4];
            float4 a1 = *(const float4*)&As[kk][64 + ty * 4];
            float4 b0 = *(const float4*)&Bs[kk][tx * 4];
            float4 b1 = *(const float4*)&Bs[kk][64 + tx * 4];
            float am[8] = {a0.x, a0.y, a0.z, a0.w, a1.x, a1.y, a1.z, a1.w};
            float bn[8] = {b0.x, b0.y, b0.z, b0.w, b1.x, b1.y, b1.z, b1.w};
#pragma unroll
            for (int i = 0; i < 8; i++)
#pragma unroll
                for (int j = 0; j < 8; j++) acc[i][j] += am[i] * bn[j];
        }
        __syncthreads();
    }

    // --- store with bias ---
#pragma unroll
    for (int i = 0; i < 8; i++) {
        int m = mBase + ((i < 4) ? (ty * 4 + i) : (64 + ty * 4 + i - 4));
        if (m >= M) continue;
#pragma unroll
        for (int j = 0; j < 8; j++) {
            int n = nBase + ((j < 4) ? (tx * 4 + j) : (64 + tx * 4 + j - 4));
            C[(size_t)m * N + n] = acc[i][j] + bias[n];
        }
    }
}

// ============================================================
// Fused attention: per CTA = (v-split s, head h, batch b)
// scores[v,l] = sum_e key[v,h,e] * q[b,l,h,e]   (VT x 128 tile)
// softmax over l (row-wise), then O[l,e] += attn^T @ value
// Partials written per split; reduced later. Deterministic.
// ============================================================
__global__ __launch_bounds__(256) void attn_kernel(
    const float* __restrict__ q, const float* __restrict__ key,
    const float* __restrict__ val, float* __restrict__ part)
{
    __shared__ float qs[EE][132];    // qs[e][l]
    __shared__ float Ks[VT][33];     // Ks[v][e]
    __shared__ float Vs[VT][34];     // Vs[v][e]
    __shared__ float Ats[VT][132];   // attn[v][l]

    int t = threadIdx.x;
    int s = blockIdx.x, h = blockIdx.y, b = blockIdx.z;
    int tx = t & 15;
    int ty = t >> 4;

    // load q[b,:,h,:] as qs[e][l]
    for (int i = t; i < EE * LL; i += 256) {
        int l = i >> 5, e = i & 31;
        qs[e][l] = q[((size_t)(b * LL + l) * HH + h) * EE + e];
    }
    __syncthreads();

    int chunk = (VV + SPLITS - 1) / SPLITS;
    int v0 = s * chunk;
    int vEnd = v0 + chunk;
    if (vEnd > VV) vEnd = VV;

    float o[8][2];
#pragma unroll
    for (int i = 0; i < 8; i++) { o[i][0] = 0.f; o[i][1] = 0.f; }

    const float scale = 0.17677669529663687f;  // 1/sqrt(32)

    int ldRow = t >> 3;          // 0..31
    int ldC4  = (t & 7) * 4;     // 0..28

    for (int vt = v0; vt < vEnd; vt += VT) {
        __syncthreads();  // protect Ks/Vs/Ats from previous iteration's readers
        // load key/value tile slices for this head
        {
            float4 kv, vv4;
            if (vt + ldRow < vEnd) {
                kv  = *(const float4*)(key + (size_t)(vt + ldRow) * DM + h * EE + ldC4);
                vv4 = *(const float4*)(val + (size_t)(vt + ldRow) * DM + h * EE + ldC4);
            } else {
                kv = make_float4(0.f, 0.f, 0.f, 0.f);
                vv4 = kv;
            }
            Ks[ldRow][ldC4 + 0] = kv.x;  Ks[ldRow][ldC4 + 1] = kv.y;
            Ks[ldRow][ldC4 + 2] = kv.z;  Ks[ldRow][ldC4 + 3] = kv.w;
            Vs[ldRow][ldC4 + 0] = vv4.x; Vs[ldRow][ldC4 + 1] = vv4.y;
            Vs[ldRow][ldC4 + 2] = vv4.z; Vs[ldRow][ldC4 + 3] = vv4.w;
        }
        __syncthreads();

        // scores: thread owns 2 v-rows x 8 l-cols
        float sc[2][8];
#pragma unroll
        for (int j = 0; j < 2; j++)
#pragma unroll
            for (int i = 0; i < 8; i++) sc[j][i] = 0.f;

#pragma unroll
        for (int e = 0; e < EE; e++) {
            float a0 = Ks[ty * 2 + 0][e];
            float a1 = Ks[ty * 2 + 1][e];
            float4 q0 = *(const float4*)&qs[e][tx * 8];
            float4 q1 = *(const float4*)&qs[e][tx * 8 + 4];
            float qq[8] = {q0.x, q0.y, q0.z, q0.w, q1.x, q1.y, q1.z, q1.w};
#pragma unroll
            for (int i = 0; i < 8; i++) {
                sc[0][i] += a0 * qq[i];
                sc[1][i] += a1 * qq[i];
            }
        }

        // softmax over l (128 values spread across 16 tx lanes)
#pragma unroll
        for (int j = 0; j < 2; j++) {
            float m = -1e30f;
#pragma unroll
            for (int i = 0; i < 8; i++) {
                sc[j][i] *= scale;
                m = fmaxf(m, sc[j][i]);
            }
#pragma unroll
            for (int ofs = 1; ofs < 16; ofs <<= 1)
                m = fmaxf(m, __shfl_xor_sync(0xffffffffu, m, ofs));
            float d = 0.f;
#pragma unroll
            for (int i = 0; i < 8; i++) {
                float p = __expf(sc[j][i] - m);
                sc[j][i] = p;
                d += p;
            }
#pragma unroll
            for (int ofs = 1; ofs < 16; ofs <<= 1)
                d += __shfl_xor_sync(0xffffffffu, d, ofs);
            float rinv = 1.f / d;
#pragma unroll
            for (int i = 0; i < 8; i++)
                Ats[ty * 2 + j][tx * 8 + i] = sc[j][i] * rinv;
        }
        __syncthreads();

        // O[l,e] += sum_v attn[v,l] * Vs[v,e]; thread owns 8 l x 2 e
#pragma unroll 8
        for (int vv = 0; vv < VT; vv++) {
            float4 p0 = *(const float4*)&Ats[vv][ty * 8];
            float4 p1 = *(const float4*)&Ats[vv][ty * 8 + 4];
            float ve0 = Vs[vv][tx * 2 + 0];
            float ve1 = Vs[vv][tx * 2 + 1];
            float pp[8] = {p0.x, p0.y, p0.z, p0.w, p1.x, p1.y, p1.z, p1.w};
#pragma unroll
            for (int i = 0; i < 8; i++) {
                o[i][0] += pp[i] * ve0;
                o[i][1] += pp[i] * ve1;
            }
        }
    }

    // write split partial: part[((b*H+h)*SPLITS+s)][l][e]
    float* pout = part + (size_t)((b * HH + h) * SPLITS + s) * LL * EE;
#pragma unroll
    for (int i = 0; i < 8; i++) {
        int l = ty * 8 + i;
        pout[l * EE + tx * 2 + 0] = o[i][0];
        pout[l * EE + tx * 2 + 1] = o[i][1];
    }
}

// ============================================================
// Reduce split partials -> reprog[b,l,h,e] (natural [512,256] layout)
// ============================================================
__global__ void reduce_part(const float* __restrict__ part, float* __restrict__ reprog)
{
    int t = blockIdx.x * blockDim.x + threadIdx.x;
    if (t >= BB * LL * DM) return;
    int e = t & 31;
    int h = (t >> 5) & 7;
    int l = (t >> 8) & 127;
    int b = t >> 15;
    const float* p = part + (size_t)(b * HH + h) * SPLITS * LL * EE + l * EE + e;
    float acc = 0.f;
#pragma unroll
    for (int s2 = 0; s2 < SPLITS; s2++) acc += p[(size_t)s2 * LL * EE];
    reprog[t] = acc;
}

// ============================================================
// Launch
// ============================================================
extern "C" void kernel_launch(void* const* d_in, const int* in_sizes, int n_in,
                              void* d_out, int out_size)
{
    (void)in_sizes; (void)n_in; (void)out_size;
    const float* ts = (const float*)d_in[0];  // [4,128,256]
    const float* we = (const float*)d_in[1];  // [50257,768]
    const float* Wq = (const float*)d_in[2];
    const float* bq = (const float*)d_in[3];
    const float* Wk = (const float*)d_in[4];
    const float* bk = (const float*)d_in[5];
    const float* Wv = (const float*)d_in[6];
    const float* bv = (const float*)d_in[7];
    const float* Wo = (const float*)d_in[8];
    const float* bo = (const float*)d_in[9];
    float* out = (float*)d_out;

    float *gq, *gk, *gv, *gp, *gr;
    cudaGetSymbolAddress((void**)&gq, g_query);
    cudaGetSymbolAddress((void**)&gk, g_key);
    cudaGetSymbolAddress((void**)&gv, g_value);
    cudaGetSymbolAddress((void**)&gp, g_part);
    cudaGetSymbolAddress((void**)&gr, g_reprog);

    dim3 thr(256);
    // Q projection: [512,256] = ts @ Wq + bq
    sgemm_bias<<<dim3((BB * LL + 127) / 128, DM / 128), thr>>>(ts, Wq, bq, gq, BB * LL, DM, DM);
    // K projection: [50257,256] = we @ Wk + bk
    sgemm_bias<<<dim3((VV + 127) / 128, DM / 128), thr>>>(we, Wk, bk, gk, VV, DM, DW);
    // V projection
    sgemm_bias<<<dim3((VV + 127) / 128, DM / 128), thr>>>(we, Wv, bv, gv, VV, DM, DW);
    // fused scores->softmax->attn@V with split-K partials
    attn_kernel<<<dim3(SPLITS, HH, BB), thr>>>(gq, gk, gv, gp);
    // reduce partials
    reduce_part<<<(BB * LL * DM + 255) / 256, 256>>>(gp, gr);
    // output projection: out = reprog @ Wo + bo
    sgemm_bias<<<dim3((BB * LL + 127) / 128, DM / 128), thr>>>(gr, Wo, bo, out, BB * LL, DM, DM);
}

// round 3
// speedup vs baseline: 1.7124x; 1.7124x over previous
#include <cuda_runtime.h>
#include <cuda_bf16.h>

#define BB 4
#define LL 128
#define DM 256
#define VV 50257
#define VPAD 50304          /* 393 * 128 */
#define DW 768
#define HH 8
#define EE 32
#define SPLITS 28
#define VT 64

// ---- scratch (static device allocations; no cudaMalloc anywhere) ----
__device__ float g_query[BB * LL * DM];
__device__ float g_key[(size_t)VV * DM];
__device__ float g_value[(size_t)VV * DM];
__device__ float g_part[BB * HH * SPLITS * LL * EE];
__device__ float g_reprog[BB * LL * DM];
__device__ __nv_bfloat16 g_Ah[(size_t)VPAD * DW];
__device__ __nv_bfloat16 g_Al[(size_t)VPAD * DW];
__device__ __nv_bfloat16 g_Wkh[(size_t)DM * DW];   // transposed [N=256][K=768]
__device__ __nv_bfloat16 g_Wkl[(size_t)DM * DW];
__device__ __nv_bfloat16 g_Wvh[(size_t)DM * DW];
__device__ __nv_bfloat16 g_Wvl[(size_t)DM * DW];

// ============================================================
// portable PTX helpers (sm_80-level only; no tcgen05 / sm_103a ISA)
// ============================================================
__device__ __forceinline__ unsigned smem_u32(const void* p) {
    unsigned a;
    asm("{ .reg .u64 t; cvta.to.shared.u64 t, %1; cvt.u32.u64 %0, t; }" : "=r"(a) : "l"(p));
    return a;
}
__device__ __forceinline__ void cp_async16(unsigned dst, const void* src) {
    asm volatile("cp.async.cg.shared.global [%0], [%1], 16;" :: "r"(dst), "l"(src));
}
#define CP_COMMIT() asm volatile("cp.async.commit_group;" ::: "memory")
#define CP_WAIT(n)  asm volatile("cp.async.wait_group %0;" :: "n"(n) : "memory")

__device__ __forceinline__ void ldsm_x4(unsigned* r, unsigned addr) {
    asm volatile("ldmatrix.sync.aligned.m8n8.x4.shared.b16 {%0,%1,%2,%3}, [%4];"
                 : "=r"(r[0]), "=r"(r[1]), "=r"(r[2]), "=r"(r[3]) : "r"(addr));
}
__device__ __forceinline__ void ldsm_x2(unsigned* r, unsigned addr) {
    asm volatile("ldmatrix.sync.aligned.m8n8.x2.shared.b16 {%0,%1}, [%2];"
                 : "=r"(r[0]), "=r"(r[1]) : "r"(addr));
}
__device__ __forceinline__ void mma16816(float* c, const unsigned* a, const unsigned* b) {
    asm volatile("mma.sync.aligned.m16n8k16.row.col.f32.bf16.bf16.f32 "
                 "{%0,%1,%2,%3}, {%4,%5,%6,%7}, {%8,%9}, {%0,%1,%2,%3};"
                 : "+f"(c[0]), "+f"(c[1]), "+f"(c[2]), "+f"(c[3])
                 : "r"(a[0]), "r"(a[1]), "r"(a[2]), "r"(a[3]), "r"(b[0]), "r"(b[1]));
}

// ============================================================
// conversion kernels: fp32 -> bf16 hi/lo split
// ============================================================
__global__ void conv_a(const float* __restrict__ A, __nv_bfloat16* __restrict__ Ah,
                       __nv_bfloat16* __restrict__ Al)
{
    size_t i4 = (size_t)blockIdx.x * blockDim.x + threadIdx.x;
    size_t total = (size_t)VPAD * DW / 4;
    if (i4 >= total) return;
    size_t off = i4 * 4;
    size_t row = off / DW;
    float4 v = make_float4(0.f, 0.f, 0.f, 0.f);
    if (row < VV) v = *(const float4*)(A + off);
    float vv[4] = {v.x, v.y, v.z, v.w};
    __nv_bfloat16 h[4], l[4];
#pragma unroll
    for (int j = 0; j < 4; j++) {
        h[j] = __float2bfloat16(vv[j]);
        l[j] = __float2bfloat16(vv[j] - __bfloat162float(h[j]));
    }
    *(__nv_bfloat162*)(Ah + off)     = __nv_bfloat162(h[0], h[1]);
    *(__nv_bfloat162*)(Ah + off + 2) = __nv_bfloat162(h[2], h[3]);
    *(__nv_bfloat162*)(Al + off)     = __nv_bfloat162(l[0], l[1]);
    *(__nv_bfloat162*)(Al + off + 2) = __nv_bfloat162(l[2], l[3]);
}

// transpose + split: W[768][256] -> Wh/Wl [256][768]
__global__ void conv_w(const float* __restrict__ W, __nv_bfloat16* __restrict__ Wh,
                       __nv_bfloat16* __restrict__ Wl)
{
    __shared__ float tile[32][33];
    int k0 = blockIdx.x * 32, n0 = blockIdx.y * 32;
    int tx = threadIdx.x, ty = threadIdx.y;  // 32 x 8
    for (int r = ty; r < 32; r += 8)
        tile[r][tx] = W[(size_t)(k0 + r) * DM + n0 + tx];
    __syncthreads();
    for (int r = ty; r < 32; r += 8) {
        float v = tile[tx][r];  // W[k0+tx][n0+r]
        __nv_bfloat16 h = __float2bfloat16(v);
        __nv_bfloat16 l = __float2bfloat16(v - __bfloat162float(h));
        Wh[(size_t)(n0 + r) * DW + k0 + tx] = h;
        Wl[(size_t)(n0 + r) * DW + k0 + tx] = l;
    }
}

// ============================================================
// mma.sync bf16 projection GEMM with 3-term split:
//   out[50257,256] = A[50257,768] @ W[768,256] + bias
//   D = Ah*Wh + Ah*Wl + Al*Wh  (fp32 accumulate)
// CTA: 128 x 256, 16 warps each 64x32. BK=32, double-buffered cp.async.
// ============================================================
#define BK 32
#define ASTR 80                          /* padded row stride bytes */
#define STG_AH 0
#define STG_AL (128 * ASTR)              /* 10240 */
#define STG_WH (2 * 128 * ASTR)          /* 20480 */
#define STG_WL (STG_WH + 256 * ASTR)     /* 40960 */
#define STG_SZ (STG_WL + 256 * ASTR)     /* 61440 */
#define KV_SMEM (2 * STG_SZ)             /* 120 KB */
#define NCH (DW / BK)                    /* 24 */

__global__ void __launch_bounds__(512, 1)
kv_gemm(const __nv_bfloat16* __restrict__ Ah, const __nv_bfloat16* __restrict__ Al,
        const __nv_bfloat16* __restrict__ Wh, const __nv_bfloat16* __restrict__ Wl,
        const float* __restrict__ bias, float* __restrict__ out)
{
    extern __shared__ char smem[];
    unsigned sb = smem_u32(smem);
    int t = threadIdx.x, lane = t & 31, wid = t >> 5;
    int mBase = blockIdx.x * 128;
    int wm = (wid & 1) * 64;        // warp m-offset within CTA tile
    int wn = (wid >> 1) * 32;       // warp n-offset

    float acc[4][4][4];
#pragma unroll
    for (int i = 0; i < 4; i++)
#pragma unroll
        for (int j = 0; j < 4; j++)
#pragma unroll
            for (int k = 0; k < 4; k++) acc[i][j][k] = 0.f;

    // per-lane ldmatrix base offsets
    unsigned a_lof = (unsigned)((lane & 15) * ASTR + (lane >> 4) * 16);
    int l2 = lane & 15;
    unsigned w_lof = (unsigned)((l2 & 7) * ASTR + (l2 >> 3) * 16);

    // ---- stage loader: 6 cp.async16 per thread ----
    auto load_stage = [&](int s, int k0) {
        unsigned stg = sb + s * STG_SZ;
        {
            int row = t >> 2, ch = t & 3;
            size_t go = (size_t)(mBase + row) * DW + k0 + ch * 8;
            unsigned d = stg + STG_AH + row * ASTR + ch * 16;
            cp_async16(d, Ah + go);
            cp_async16(d + (STG_AL - STG_AH), Al + go);
        }
#pragma unroll
        for (int r2 = 0; r2 < 2; r2++) {
            int i = t + r2 * 512;
            int row = i >> 2, ch = i & 3;
            size_t go = (size_t)row * DW + k0 + ch * 8;
            unsigned d = stg + STG_WH + row * ASTR + ch * 16;
            cp_async16(d, Wh + go);
            cp_async16(d + (STG_WL - STG_WH), Wl + go);
        }
    };

    load_stage(0, 0);
    CP_COMMIT();

    for (int c = 0; c < NCH; c++) {
        if (c + 1 < NCH) {
            load_stage((c + 1) & 1, (c + 1) * BK);
            CP_COMMIT();
            CP_WAIT(1);
        } else {
            CP_WAIT(0);
        }
        __syncthreads();

        unsigned stg = sb + (c & 1) * STG_SZ;
        unsigned aH = stg + STG_AH + wm * ASTR + a_lof;
        unsigned aL = stg + STG_AL + wm * ASTR + a_lof;
        unsigned wH = stg + STG_WH + wn * ASTR + w_lof;
        unsigned wL = stg + STG_WL + wn * ASTR + w_lof;

#pragma unroll
        for (int ks = 0; ks < 2; ks++) {
            unsigned kb = ks * 32;  // 16 bf16 = 32 bytes
            unsigned a[4][4], bh[4][2], bl[4][2];
#pragma unroll
            for (int mt = 0; mt < 4; mt++) ldsm_x4(a[mt], aH + mt * (16 * ASTR) + kb);
#pragma unroll
            for (int nt = 0; nt < 4; nt++) {
                ldsm_x2(bh[nt], wH + nt * (8 * ASTR) + kb);
                ldsm_x2(bl[nt], wL + nt * (8 * ASTR) + kb);
            }
#pragma unroll
            for (int mt = 0; mt < 4; mt++)
#pragma unroll
                for (int nt = 0; nt < 4; nt++) mma16816(acc[mt][nt], a[mt], bh[nt]);
#pragma unroll
            for (int mt = 0; mt < 4; mt++)
#pragma unroll
                for (int nt = 0; nt < 4; nt++) mma16816(acc[mt][nt], a[mt], bl[nt]);
#pragma unroll
            for (int mt = 0; mt < 4; mt++) ldsm_x4(a[mt], aL + mt * (16 * ASTR) + kb);
#pragma unroll
            for (int mt = 0; mt < 4; mt++)
#pragma unroll
                for (int nt = 0; nt < 4; nt++) mma16816(acc[mt][nt], a[mt], bh[nt]);
        }
        __syncthreads();
    }

    // ---- epilogue ----
    int gid = lane >> 2, tig = lane & 3;
#pragma unroll
    for (int nt = 0; nt < 4; nt++) {
        int col = wn + nt * 8 + tig * 2;
        float2 bv = *(const float2*)(bias + col);
#pragma unroll
        for (int mt = 0; mt < 4; mt++) {
            int r0 = mBase + wm + mt * 16 + gid;
            int r1 = r0 + 8;
            if (r0 < VV) {
                float2 o;
                o.x = acc[mt][nt][0] + bv.x;
                o.y = acc[mt][nt][1] + bv.y;
                *(float2*)(out + (size_t)r0 * DM + col) = o;
            }
            if (r1 < VV) {
                float2 o;
                o.x = acc[mt][nt][2] + bv.x;
                o.y = acc[mt][nt][3] + bv.y;
                *(float2*)(out + (size_t)r1 * DM + col) = o;
            }
        }
    }
}

// ============================================================
// fp32 SGEMM (small Q / O projections): C = A @ B + bias
// ============================================================
__global__ __launch_bounds__(256) void sgemm_bias(
    const float* __restrict__ A, const float* __restrict__ Bw,
    const float* __restrict__ bias, float* __restrict__ C,
    int M, int N, int K)
{
    __shared__ float As[16][132];
    __shared__ float Bs[16][132];
    int t = threadIdx.x, tx = t & 15, ty = t >> 4;
    int mBase = blockIdx.x * 128, nBase = blockIdx.y * 128;
    float acc[8][8];
#pragma unroll
    for (int i = 0; i < 8; i++)
#pragma unroll
        for (int j = 0; j < 8; j++) acc[i][j] = 0.f;

    for (int k0 = 0; k0 < K; k0 += 16) {
#pragma unroll
        for (int r = 0; r < 2; r++) {
            int idx = t * 2 + r;
            int row = idx >> 2, k4 = (idx & 3) * 4;
            float4 av = make_float4(0.f, 0.f, 0.f, 0.f);
            if (mBase + row < M)
                av = *(const float4*)(A + (size_t)(mBase + row) * K + k0 + k4);
            As[k4 + 0][row] = av.x; As[k4 + 1][row] = av.y;
            As[k4 + 2][row] = av.z; As[k4 + 3][row] = av.w;
        }
#pragma unroll
        for (int r = 0; r < 2; r++) {
            int idx = t * 2 + r;
            int kr = idx >> 5, c4 = (idx & 31) * 4;
            *(float4*)&Bs[kr][c4] = *(const float4*)(Bw + (size_t)(k0 + kr) * N + nBase + c4);
        }
        __syncthreads();
#pragma unroll
        for (int kk = 0; kk < 16; kk++) {
            float4 a0 = *(const float4*)&As[kk][ty * 4];
            float4 a1 = *(const float4*)&As[kk][64 + ty * 4];
            float4 b0 = *(const float4*)&Bs[kk][tx * 4];
            float4 b1 = *(const float4*)&Bs[kk][64 + tx * 4];
            float am[8] = {a0.x, a0.y, a0.z, a0.w, a1.x, a1.y, a1.z, a1.w};
            float bn[8] = {b0.x, b0.y, b0.z, b0.w, b1.x, b1.y, b1.z, b1.w};
#pragma unroll
            for (int i = 0; i < 8; i++)
#pragma unroll
                for (int j = 0; j < 8; j++) acc[i][j] += am[i] * bn[j];
        }
        __syncthreads();
    }
#pragma unroll
    for (int i = 0; i < 8; i++) {
        int m = mBase + ((i < 4) ? (ty * 4 + i) : (64 + ty * 4 + i - 4));
        if (m >= M) continue;
#pragma unroll
        for (int j = 0; j < 8; j++) {
            int n = nBase + ((j < 4) ? (tx * 4 + j) : (64 + tx * 4 + j - 4));
            C[(size_t)m * N + n] = acc[i][j] + bias[n];
        }
    }
}

// ============================================================
// Fused attention (fp32 SIMT, VT=64, 4 v-rows/thread in scores)
// ============================================================
#define ATTN_SMEM ((32 * 132 + VT * 33 + VT * 34 + VT * 132) * 4)

__global__ __launch_bounds__(256) void attn_kernel(
    const float* __restrict__ q, const float* __restrict__ key,
    const float* __restrict__ val, float* __restrict__ part)
{
    extern __shared__ float sm[];
    float* qs  = sm;                   // [32][132]
    float* Ks  = qs + 32 * 132;        // [VT][33]
    float* Vs  = Ks + VT * 33;         // [VT][34]
    float* Ats = Vs + VT * 34;         // [VT][132]

    int t = threadIdx.x;
    int s = blockIdx.x, h = blockIdx.y, b = blockIdx.z;
    int tx = t & 15;
    int ty = t >> 4;

    for (int i = t; i < EE * LL; i += 256) {
        int l = i >> 5, e = i & 31;
        qs[e * 132 + l] = q[((size_t)(b * LL + l) * HH + h) * EE + e];
    }
    __syncthreads();

    int chunk = (VV + SPLITS - 1) / SPLITS;
    int v0 = s * chunk;
    int vEnd = v0 + chunk;
    if (vEnd > VV) vEnd = VV;

    float o[8][2];
#pragma unroll
    for (int i = 0; i < 8; i++) { o[i][0] = 0.f; o[i][1] = 0.f; }

    const float scale = 0.17677669529663687f;

    for (int vt = v0; vt < vEnd; vt += VT) {
        __syncthreads();
#pragma unroll
        for (int r2 = 0; r2 < 2; r2++) {
            int idx = t * 2 + r2;
            int row = idx >> 3, c4 = (idx & 7) * 4;
            float4 kv = make_float4(0.f, 0.f, 0.f, 0.f), vv4 = kv;
            if (vt + row < vEnd) {
                kv  = *(const float4*)(key + (size_t)(vt + row) * DM + h * EE + c4);
                vv4 = *(const float4*)(val + (size_t)(vt + row) * DM + h * EE + c4);
            }
            Ks[row * 33 + c4 + 0] = kv.x;  Ks[row * 33 + c4 + 1] = kv.y;
            Ks[row * 33 + c4 + 2] = kv.z;  Ks[row * 33 + c4 + 3] = kv.w;
            Vs[row * 34 + c4 + 0] = vv4.x; Vs[row * 34 + c4 + 1] = vv4.y;
            Vs[row * 34 + c4 + 2] = vv4.z; Vs[row * 34 + c4 + 3] = vv4.w;
        }
        __syncthreads();

        float sc[4][8];
#pragma unroll
        for (int j = 0; j < 4; j++)
#pragma unroll
            for (int i = 0; i < 8; i++) sc[j][i] = 0.f;

#pragma unroll
        for (int e = 0; e < EE; e++) {
            float a0 = Ks[(ty * 4 + 0) * 33 + e];
            float a1 = Ks[(ty * 4 + 1) * 33 + e];
            float a2 = Ks[(ty * 4 + 2) * 33 + e];
            float a3 = Ks[(ty * 4 + 3) * 33 + e];
            float4 q0 = *(const float4*)&qs[e * 132 + tx * 8];
            float4 q1 = *(const float4*)&qs[e * 132 + tx * 8 + 4];
            float qq[8] = {q0.x, q0.y, q0.z, q0.w, q1.x, q1.y, q1.z, q1.w};
#pragma unroll
            for (int i = 0; i < 8; i++) {
                sc[0][i] += a0 * qq[i];
                sc[1][i] += a1 * qq[i];
                sc[2][i] += a2 * qq[i];
                sc[3][i] += a3 * qq[i];
            }
        }

#pragma unroll
        for (int j = 0; j < 4; j++) {
            float m = -1e30f;
#pragma unroll
            for (int i = 0; i < 8; i++) {
                sc[j][i] *= scale;
                m = fmaxf(m, sc[j][i]);
            }
#pragma unroll
            for (int ofs = 1; ofs < 16; ofs <<= 1)
                m = fmaxf(m, __shfl_xor_sync(0xffffffffu, m, ofs));
            float d = 0.f;
#pragma unroll
            for (int i = 0; i < 8; i++) {
                float p = __expf(sc[j][i] - m);
                sc[j][i] = p;
                d += p;
            }
#pragma unroll
            for (int ofs = 1; ofs < 16; ofs <<= 1)
                d += __shfl_xor_sync(0xffffffffu, d, ofs);
            float rinv = 1.f / d;
#pragma unroll
            for (int i = 0; i < 8; i++)
                Ats[(ty * 4 + j) * 132 + tx * 8 + i] = sc[j][i] * rinv;
        }
        __syncthreads();

#pragma unroll 8
        for (int vv = 0; vv < VT; vv++) {
            float4 p0 = *(const float4*)&Ats[vv * 132 + ty * 8];
            float4 p1 = *(const float4*)&Ats[vv * 132 + ty * 8 + 4];
            float ve0 = Vs[vv * 34 + tx * 2 + 0];
            float ve1 = Vs[vv * 34 + tx * 2 + 1];
            float pp[8] = {p0.x, p0.y, p0.z, p0.w, p1.x, p1.y, p1.z, p1.w};
#pragma unroll
            for (int i = 0; i < 8; i++) {
                o[i][0] += pp[i] * ve0;
                o[i][1] += pp[i] * ve1;
            }
        }
    }

    float* pout = part + (size_t)((b * HH + h) * SPLITS + s) * LL * EE;
#pragma unroll
    for (int i = 0; i < 8; i++) {
        int l = ty * 8 + i;
        pout[l * EE + tx * 2 + 0] = o[i][0];
        pout[l * EE + tx * 2 + 1] = o[i][1];
    }
}

__global__ void reduce_part(const float* __restrict__ part, float* __restrict__ reprog)
{
    int t = blockIdx.x * blockDim.x + threadIdx.x;
    if (t >= BB * LL * DM) return;
    int e = t & 31;
    int h = (t >> 5) & 7;
    int l = (t >> 8) & 127;
    int b = t >> 15;
    const float* p = part + (size_t)(b * HH + h) * SPLITS * LL * EE + l * EE + e;
    float acc = 0.f;
#pragma unroll
    for (int s2 = 0; s2 < SPLITS; s2++) acc += p[(size_t)s2 * LL * EE];
    reprog[t] = acc;
}

// ============================================================
// Launch
// ============================================================
extern "C" void kernel_launch(void* const* d_in, const int* in_sizes, int n_in,
                              void* d_out, int out_size)
{
    (void)in_sizes; (void)n_in; (void)out_size;
    const float* ts = (const float*)d_in[0];
    const float* we = (const float*)d_in[1];
    const float* Wq = (const float*)d_in[2];
    const float* bq = (const float*)d_in[3];
    const float* Wk = (const float*)d_in[4];
    const float* bk = (const float*)d_in[5];
    const float* Wv = (const float*)d_in[6];
    const float* bv = (const float*)d_in[7];
    const float* Wo = (const float*)d_in[8];
    const float* bo = (const float*)d_in[9];
    float* out = (float*)d_out;

    float *gq, *gk, *gv, *gp, *gr;
    __nv_bfloat16 *ah, *al, *wkh, *wkl, *wvh, *wvl;
    cudaGetSymbolAddress((void**)&gq, g_query);
    cudaGetSymbolAddress((void**)&gk, g_key);
    cudaGetSymbolAddress((void**)&gv, g_value);
    cudaGetSymbolAddress((void**)&gp, g_part);
    cudaGetSymbolAddress((void**)&gr, g_reprog);
    cudaGetSymbolAddress((void**)&ah, g_Ah);
    cudaGetSymbolAddress((void**)&al, g_Al);
    cudaGetSymbolAddress((void**)&wkh, g_Wkh);
    cudaGetSymbolAddress((void**)&wkl, g_Wkl);
    cudaGetSymbolAddress((void**)&wvh, g_Wvh);
    cudaGetSymbolAddress((void**)&wvl, g_Wvl);

    cudaFuncSetAttribute(kv_gemm, cudaFuncAttributeMaxDynamicSharedMemorySize, KV_SMEM);
    cudaFuncSetAttribute(attn_kernel, cudaFuncAttributeMaxDynamicSharedMemorySize, ATTN_SMEM);

    // conversions
    {
        size_t tot4 = (size_t)VPAD * DW / 4;
        conv_a<<<(unsigned)((tot4 + 255) / 256), 256>>>(we, ah, al);
        dim3 wb(32, 8);
        conv_w<<<dim3(DW / 32, DM / 32), wb>>>(Wk, wkh, wkl);
        conv_w<<<dim3(DW / 32, DM / 32), wb>>>(Wv, wvh, wvl);
    }
    // Q projection (fp32, small)
    sgemm_bias<<<dim3((BB * LL + 127) / 128, DM / 128), 256>>>(ts, Wq, bq, gq, BB * LL, DM, DM);
    // K / V projections (mma.sync bf16, 3-term split)
    kv_gemm<<<VPAD / 128, 512, KV_SMEM>>>(ah, al, wkh, wkl, bk, gk);
    kv_gemm<<<VPAD / 128, 512, KV_SMEM>>>(ah, al, wvh, wvl, bv, gv);
    // attention
    attn_kernel<<<dim3(SPLITS, HH, BB), 256, ATTN_SMEM>>>(gq, gk, gv, gp);
    reduce_part<<<(BB * LL * DM + 255) / 256, 256>>>(gp, gr);
    // output projection
    sgemm_bias<<<dim3((BB * LL + 127) / 128, DM / 128), 256>>>(gr, Wo, bo, out, BB * LL, DM, DM);
}

// round 4
// speedup vs baseline: 2.9600x; 1.7286x over previous
#include <cuda_runtime.h>
#include <cuda_bf16.h>

#define BB 4
#define LL 128
#define DM 256
#define VV 50257
#define VPAD 50304          /* 393 * 128 */
#define NTILE 393
#define DW 768
#define HH 8
#define EE 32
#define SPLITS 9

// ---- scratch (static device allocations; no cudaMalloc anywhere) ----
__device__ float g_query[BB * LL * DM];
__device__ float g_part[BB * HH * SPLITS * LL * EE];
__device__ float g_reprog[BB * LL * DM];
__device__ __nv_bfloat16 g_Ah[(size_t)VPAD * DW];
__device__ __nv_bfloat16 g_Al[(size_t)VPAD * DW];
__device__ __nv_bfloat16 g_Wkh[(size_t)DM * DW];
__device__ __nv_bfloat16 g_Wkl[(size_t)DM * DW];
__device__ __nv_bfloat16 g_Wvh[(size_t)DM * DW];
__device__ __nv_bfloat16 g_Wvl[(size_t)DM * DW];
__device__ __nv_bfloat16 g_Kh[(size_t)VPAD * DM];
__device__ __nv_bfloat16 g_Kl[(size_t)VPAD * DM];
__device__ __nv_bfloat16 g_Vh[(size_t)VPAD * DM];
__device__ __nv_bfloat16 g_Vl[(size_t)VPAD * DM];
__device__ __nv_bfloat16 g_Qh[BB * LL * DM];
__device__ __nv_bfloat16 g_Ql[BB * LL * DM];

// ============================================================
// portable PTX helpers (sm_80-level; no sm_103a-only ISA)
// ============================================================
__device__ __forceinline__ unsigned smem_u32(const void* p) {
    unsigned a;
    asm("{ .reg .u64 t; cvta.to.shared.u64 t, %1; cvt.u32.u64 %0, t; }" : "=r"(a) : "l"(p));
    return a;
}
__device__ __forceinline__ void cp_async16(unsigned dst, const void* src) {
    asm volatile("cp.async.cg.shared.global [%0], [%1], 16;" :: "r"(dst), "l"(src));
}
#define CP_COMMIT() asm volatile("cp.async.commit_group;" ::: "memory")
#define CP_WAIT(n)  asm volatile("cp.async.wait_group %0;" :: "n"(n) : "memory")

__device__ __forceinline__ void ldsm_x4(unsigned* r, unsigned addr) {
    asm volatile("ldmatrix.sync.aligned.m8n8.x4.shared.b16 {%0,%1,%2,%3}, [%4];"
                 : "=r"(r[0]), "=r"(r[1]), "=r"(r[2]), "=r"(r[3]) : "r"(addr));
}
__device__ __forceinline__ void ldsm_x2(unsigned* r, unsigned addr) {
    asm volatile("ldmatrix.sync.aligned.m8n8.x2.shared.b16 {%0,%1}, [%2];"
                 : "=r"(r[0]), "=r"(r[1]) : "r"(addr));
}
__device__ __forceinline__ void ldsm_x4_t(unsigned* r, unsigned addr) {
    asm volatile("ldmatrix.sync.aligned.m8n8.x4.trans.shared.b16 {%0,%1,%2,%3}, [%4];"
                 : "=r"(r[0]), "=r"(r[1]), "=r"(r[2]), "=r"(r[3]) : "r"(addr));
}
__device__ __forceinline__ void ldsm_x2_t(unsigned* r, unsigned addr) {
    asm volatile("ldmatrix.sync.aligned.m8n8.x2.trans.shared.b16 {%0,%1}, [%2];"
                 : "=r"(r[0]), "=r"(r[1]) : "r"(addr));
}
__device__ __forceinline__ void mma16816(float* c, const unsigned* a, const unsigned* b) {
    asm volatile("mma.sync.aligned.m16n8k16.row.col.f32.bf16.bf16.f32 "
                 "{%0,%1,%2,%3}, {%4,%5,%6,%7}, {%8,%9}, {%0,%1,%2,%3};"
                 : "+f"(c[0]), "+f"(c[1]), "+f"(c[2]), "+f"(c[3])
                 : "r"(a[0]), "r"(a[1]), "r"(a[2]), "r"(a[3]), "r"(b[0]), "r"(b[1]));
}
__device__ __forceinline__ float ex2(float x) {
    float r;
    asm("ex2.approx.ftz.f32 %0, %1;" : "=f"(r) : "f"(x));
    return r;
}
__device__ __forceinline__ unsigned pack_bf16(float a, float b) {
    __nv_bfloat162 t(__float2bfloat16(a), __float2bfloat16(b));
    return *(unsigned*)&t;
}

// ============================================================
// conversion kernels: fp32 -> bf16 hi/lo split
// ============================================================
__global__ void conv_a(const float* __restrict__ A, __nv_bfloat16* __restrict__ Ah,
                       __nv_bfloat16* __restrict__ Al)
{
    size_t i4 = (size_t)blockIdx.x * blockDim.x + threadIdx.x;
    size_t total = (size_t)VPAD * DW / 4;
    if (i4 >= total) return;
    size_t off = i4 * 4;
    size_t row = off / DW;
    float4 v = make_float4(0.f, 0.f, 0.f, 0.f);
    if (row < VV) v = *(const float4*)(A + off);
    float vv[4] = {v.x, v.y, v.z, v.w};
    __nv_bfloat16 h[4], l[4];
#pragma unroll
    for (int j = 0; j < 4; j++) {
        h[j] = __float2bfloat16(vv[j]);
        l[j] = __float2bfloat16(vv[j] - __bfloat162float(h[j]));
    }
    *(__nv_bfloat162*)(Ah + off)     = __nv_bfloat162(h[0], h[1]);
    *(__nv_bfloat162*)(Ah + off + 2) = __nv_bfloat162(h[2], h[3]);
    *(__nv_bfloat162*)(Al + off)     = __nv_bfloat162(l[0], l[1]);
    *(__nv_bfloat162*)(Al + off + 2) = __nv_bfloat162(l[2], l[3]);
}

__global__ void conv_w(const float* __restrict__ W, __nv_bfloat16* __restrict__ Wh,
                       __nv_bfloat16* __restrict__ Wl)
{
    __shared__ float tile[32][33];
    int k0 = blockIdx.x * 32, n0 = blockIdx.y * 32;
    int tx = threadIdx.x, ty = threadIdx.y;
    for (int r = ty; r < 32; r += 8)
        tile[r][tx] = W[(size_t)(k0 + r) * DM + n0 + tx];
    __syncthreads();
    for (int r = ty; r < 32; r += 8) {
        float v = tile[tx][r];
        __nv_bfloat16 h = __float2bfloat16(v);
        __nv_bfloat16 l = __float2bfloat16(v - __bfloat162float(h));
        Wh[(size_t)(n0 + r) * DW + k0 + tx] = h;
        Wl[(size_t)(n0 + r) * DW + k0 + tx] = l;
    }
}

__global__ void conv_q(const float* __restrict__ Q, __nv_bfloat16* __restrict__ Qh,
                       __nv_bfloat16* __restrict__ Ql)
{
    int i = blockIdx.x * blockDim.x + threadIdx.x;
    if (i >= BB * LL * DM) return;
    float v = Q[i];
    __nv_bfloat16 h = __float2bfloat16(v);
    Qh[i] = h;
    Ql[i] = __float2bfloat16(v - __bfloat162float(h));
}

// ============================================================
// mma.sync bf16 projection GEMM (3-term split), bf16 hi/lo output
// ============================================================
#define BK 32
#define ASTR 80
#define STG_AH 0
#define STG_AL (128 * ASTR)
#define STG_WH (2 * 128 * ASTR)
#define STG_WL (STG_WH + 256 * ASTR)
#define STG_SZ (STG_WL + 256 * ASTR)
#define KV_SMEM (2 * STG_SZ)
#define NCH (DW / BK)

__global__ void __launch_bounds__(512, 1)
kv_gemm(const __nv_bfloat16* __restrict__ Ah, const __nv_bfloat16* __restrict__ Al,
        const __nv_bfloat16* __restrict__ Wh, const __nv_bfloat16* __restrict__ Wl,
        const float* __restrict__ bias,
        __nv_bfloat16* __restrict__ outH, __nv_bfloat16* __restrict__ outL)
{
    extern __shared__ char smem[];
    unsigned sb = smem_u32(smem);
    int t = threadIdx.x, lane = t & 31, wid = t >> 5;
    int mBase = blockIdx.x * 128;
    int wm = (wid & 1) * 64;
    int wn = (wid >> 1) * 32;

    float acc[4][4][4];
#pragma unroll
    for (int i = 0; i < 4; i++)
#pragma unroll
        for (int j = 0; j < 4; j++)
#pragma unroll
            for (int k = 0; k < 4; k++) acc[i][j][k] = 0.f;

    unsigned a_lof = (unsigned)((lane & 15) * ASTR + (lane >> 4) * 16);
    int l2 = lane & 15;
    unsigned w_lof = (unsigned)((l2 & 7) * ASTR + (l2 >> 3) * 16);

    auto load_stage = [&](int s, int k0) {
        unsigned stg = sb + s * STG_SZ;
        {
            int row = t >> 2, ch = t & 3;
            size_t go = (size_t)(mBase + row) * DW + k0 + ch * 8;
            unsigned d = stg + STG_AH + row * ASTR + ch * 16;
            cp_async16(d, Ah + go);
            cp_async16(d + (STG_AL - STG_AH), Al + go);
        }
#pragma unroll
        for (int r2 = 0; r2 < 2; r2++) {
            int i = t + r2 * 512;
            int row = i >> 2, ch = i & 3;
            size_t go = (size_t)row * DW + k0 + ch * 8;
            unsigned d = stg + STG_WH + row * ASTR + ch * 16;
            cp_async16(d, Wh + go);
            cp_async16(d + (STG_WL - STG_WH), Wl + go);
        }
    };

    load_stage(0, 0);
    CP_COMMIT();

    for (int c = 0; c < NCH; c++) {
        if (c + 1 < NCH) {
            load_stage((c + 1) & 1, (c + 1) * BK);
            CP_COMMIT();
            CP_WAIT(1);
        } else {
            CP_WAIT(0);
        }
        __syncthreads();

        unsigned stg = sb + (c & 1) * STG_SZ;
        unsigned aH = stg + STG_AH + wm * ASTR + a_lof;
        unsigned aL = stg + STG_AL + wm * ASTR + a_lof;
        unsigned wH = stg + STG_WH + wn * ASTR + w_lof;
        unsigned wL = stg + STG_WL + wn * ASTR + w_lof;

#pragma unroll
        for (int ks = 0; ks < 2; ks++) {
            unsigned kb = ks * 32;
            unsigned a[4][4], bh[4][2], bl[4][2];
#pragma unroll
            for (int mt = 0; mt < 4; mt++) ldsm_x4(a[mt], aH + mt * (16 * ASTR) + kb);
#pragma unroll
            for (int nt = 0; nt < 4; nt++) {
                ldsm_x2(bh[nt], wH + nt * (8 * ASTR) + kb);
                ldsm_x2(bl[nt], wL + nt * (8 * ASTR) + kb);
            }
#pragma unroll
            for (int mt = 0; mt < 4; mt++)
#pragma unroll
                for (int nt = 0; nt < 4; nt++) mma16816(acc[mt][nt], a[mt], bh[nt]);
#pragma unroll
            for (int mt = 0; mt < 4; mt++)
#pragma unroll
                for (int nt = 0; nt < 4; nt++) mma16816(acc[mt][nt], a[mt], bl[nt]);
#pragma unroll
            for (int mt = 0; mt < 4; mt++) ldsm_x4(a[mt], aL + mt * (16 * ASTR) + kb);
#pragma unroll
            for (int mt = 0; mt < 4; mt++)
#pragma unroll
                for (int nt = 0; nt < 4; nt++) mma16816(acc[mt][nt], a[mt], bh[nt]);
        }
        __syncthreads();
    }

    // epilogue: bf16 hi/lo output, zero padded rows
    int gid = lane >> 2, tig = lane & 3;
#pragma unroll
    for (int nt = 0; nt < 4; nt++) {
        int col = wn + nt * 8 + tig * 2;
        float2 bv = *(const float2*)(bias + col);
#pragma unroll
        for (int mt = 0; mt < 4; mt++) {
            int r0 = mBase + wm + mt * 16 + gid;
            int r1 = r0 + 8;
            float x0 = (r0 < VV) ? acc[mt][nt][0] + bv.x : 0.f;
            float x1 = (r0 < VV) ? acc[mt][nt][1] + bv.y : 0.f;
            float x2 = (r1 < VV) ? acc[mt][nt][2] + bv.x : 0.f;
            float x3 = (r1 < VV) ? acc[mt][nt][3] + bv.y : 0.f;
            __nv_bfloat16 h0 = __float2bfloat16(x0), h1 = __float2bfloat16(x1);
            __nv_bfloat16 h2 = __float2bfloat16(x2), h3 = __float2bfloat16(x3);
            *(unsigned*)(outH + (size_t)r0 * DM + col) = pack_bf16(x0, x1);
            *(unsigned*)(outL + (size_t)r0 * DM + col) =
                pack_bf16(x0 - __bfloat162float(h0), x1 - __bfloat162float(h1));
            *(unsigned*)(outH + (size_t)r1 * DM + col) = pack_bf16(x2, x3);
            *(unsigned*)(outL + (size_t)r1 * DM + col) =
                pack_bf16(x2 - __bfloat162float(h2), x3 - __bfloat162float(h3));
        }
    }
}

// ============================================================
// small fp32 SGEMM 64x64 tiles (Q / O projections)
// ============================================================
__global__ __launch_bounds__(256) void sgemm64(
    const float* __restrict__ A, const float* __restrict__ Bw,
    const float* __restrict__ bias, float* __restrict__ C,
    int M, int N, int K)
{
    __shared__ float As[16][68];
    __shared__ float Bs[16][68];
    int t = threadIdx.x, tx = t & 15, ty = t >> 4;
    int mB = blockIdx.x * 64, nB = blockIdx.y * 64;
    float acc[4][4];
#pragma unroll
    for (int i = 0; i < 4; i++)
#pragma unroll
        for (int j = 0; j < 4; j++) acc[i][j] = 0.f;

    for (int k0 = 0; k0 < K; k0 += 16) {
        {
            int row = t >> 2, kk = (t & 3) * 4;
            float4 av = *(const float4*)(A + (size_t)(mB + row) * K + k0 + kk);
            As[kk + 0][row] = av.x; As[kk + 1][row] = av.y;
            As[kk + 2][row] = av.z; As[kk + 3][row] = av.w;
        }
        {
            int kr = t >> 4, c4 = (t & 15) * 4;
            *(float4*)&Bs[kr][c4] = *(const float4*)(Bw + (size_t)(k0 + kr) * N + nB + c4);
        }
        __syncthreads();
#pragma unroll
        for (int kk = 0; kk < 16; kk++) {
            float4 a = *(const float4*)&As[kk][ty * 4];
            float4 b = *(const float4*)&Bs[kk][tx * 4];
            float am[4] = {a.x, a.y, a.z, a.w};
            float bn[4] = {b.x, b.y, b.z, b.w};
#pragma unroll
            for (int i = 0; i < 4; i++)
#pragma unroll
                for (int j = 0; j < 4; j++) acc[i][j] += am[i] * bn[j];
        }
        __syncthreads();
    }
#pragma unroll
    for (int i = 0; i < 4; i++) {
        int m = mB + ty * 4 + i;
#pragma unroll
        for (int j = 0; j < 4; j++) {
            int n = nB + tx * 4 + j;
            C[(size_t)m * N + n] = acc[i][j] + bias[n];
        }
    }
}

// ============================================================
// Tensor-core fused attention
// CTA = (split s, head h, batch b); 8 warps, 256 threads.
// Per 128-v tile:  S = K Q^T (3-term) -> softmax over l -> P hi/lo
//                  O += P^T V (3-term), partials to g_part.
// ============================================================
#define QSTR 80
#define PSTR 272
#define OFF_QH 0
#define OFF_QL 10240
#define OFF_KV 20480
#define KVBUF 40960         /* KH,KL,VH,VL each 10240 */
#define OFF_PH (20480 + 2 * KVBUF)          /* 102400 */
#define OFF_PL (OFF_PH + 128 * PSTR)        /* 137216 */
#define OFF_RED (OFF_PL + 128 * PSTR)       /* 172032 */
#define ATTN_SMEM (OFF_RED + 1024)          /* 173056 */

__global__ void __launch_bounds__(256, 1)
attn_tc(const __nv_bfloat16* __restrict__ Qh, const __nv_bfloat16* __restrict__ Ql,
        const __nv_bfloat16* __restrict__ Kh, const __nv_bfloat16* __restrict__ Kl,
        const __nv_bfloat16* __restrict__ Vh, const __nv_bfloat16* __restrict__ Vl,
        float* __restrict__ part)
{
    extern __shared__ char smem[];
    unsigned sb = smem_u32(smem);
    float* red = (float*)(smem + OFF_RED);

    int t = threadIdx.x, lane = t & 31, wid = t >> 5;
    int s = blockIdx.x, h = blockIdx.y, b = blockIdx.z;
    int gid = lane >> 2, tig = lane & 3;

    int wm = (wid & 3) * 32;       // S-phase: v rows
    int wn = (wid >> 2) * 64;      // S-phase: l cols
    int half = wid >> 2;
    int lb = wid * 16;             // O-phase: l rows

    // ---- load Q slice [128 l][32 e] hi/lo into smem ----
    {
        size_t qbase = (size_t)(b * LL) * DM + h * EE;
#pragma unroll
        for (int j = 0; j < 2; j++) {
            int idx = t + j * 256;          // 0..511
            int row = idx >> 2, c = idx & 3;
            size_t go = qbase + (size_t)row * DM + c * 8;
            unsigned d = sb + row * QSTR + c * 16;
            cp_async16(d + OFF_QH, Qh + go);
            cp_async16(d + OFF_QL, Ql + go);
        }
    }
    CP_COMMIT();
    CP_WAIT(0);
    __syncthreads();

    // ---- Q B-fragments in registers (per warp: its 64 l-cols) ----
    unsigned qhf[8][2][2], qlf[8][2][2];
    {
        int l15 = lane & 15;
        unsigned base = (unsigned)((l15 & 7) * QSTR + ((l15 >> 3) * 16));
#pragma unroll
        for (int n = 0; n < 8; n++)
#pragma unroll
            for (int k = 0; k < 2; k++) {
                unsigned off = (wn + 8 * n) * QSTR + base + k * 32;
                ldsm_x2(qhf[n][k], sb + OFF_QH + off);
                ldsm_x2(qlf[n][k], sb + OFF_QL + off);
            }
    }

    float accO[4][4];
#pragma unroll
    for (int i = 0; i < 4; i++)
#pragma unroll
        for (int j = 0; j < 4; j++) accO[i][j] = 0.f;

    // tiles for this split
    int tile0 = s;
    size_t hof = (size_t)h * EE;

    auto load_kv = [&](int buf, int v0) {
        unsigned base = sb + OFF_KV + buf * KVBUF;
#pragma unroll
        for (int j = 0; j < 2; j++) {
            int idx = t + j * 256;
            int row = idx >> 2, c = idx & 3;
            size_t go = (size_t)(v0 + row) * DM + hof + c * 8;
            unsigned d = base + row * QSTR + c * 16;
            cp_async16(d,             Kh + go);
            cp_async16(d + 10240,     Kl + go);
            cp_async16(d + 20480,     Vh + go);
            cp_async16(d + 30720,     Vl + go);
        }
    };

    load_kv(0, tile0 * 128);
    CP_COMMIT();

    const float C = 0.25503327723425473f;  // scale * log2(e)

    int it = 0;
    for (int tile = tile0; tile < NTILE; tile += SPLITS, it++) {
        int nxt = tile + SPLITS;
        if (nxt < NTILE) {
            load_kv((it + 1) & 1, nxt * 128);
            CP_COMMIT();
            CP_WAIT(1);
        } else {
            CP_WAIT(0);
        }
        __syncthreads();

        unsigned kvb = sb + OFF_KV + (it & 1) * KVBUF;

        // ---- S-GEMM: accS[2 mt][8 n][4] ----
        float accS[2][8][4];
#pragma unroll
        for (int mt = 0; mt < 2; mt++)
#pragma unroll
            for (int n = 0; n < 8; n++)
#pragma unroll
                for (int q = 0; q < 4; q++) accS[mt][n][q] = 0.f;

        {
            unsigned alof = (unsigned)((lane & 15) * QSTR + (lane >> 4) * 16);
            unsigned aH[2][2][4], aL[2][2][4];
#pragma unroll
            for (int mt = 0; mt < 2; mt++)
#pragma unroll
                for (int k = 0; k < 2; k++) {
                    unsigned off = (wm + 16 * mt) * QSTR + alof + k * 32;
                    ldsm_x4(aH[mt][k], kvb + off);            // KH
                    ldsm_x4(aL[mt][k], kvb + 10240 + off);    // KL
                }
#pragma unroll
            for (int mt = 0; mt < 2; mt++)
#pragma unroll
                for (int n = 0; n < 8; n++)
#pragma unroll
                    for (int k = 0; k < 2; k++) {
                        mma16816(accS[mt][n], aH[mt][k], qhf[n][k]);
                        mma16816(accS[mt][n], aH[mt][k], qlf[n][k]);
                        mma16816(accS[mt][n], aL[mt][k], qhf[n][k]);
                    }
        }

        // ---- exp + partial row sums (no max-sub needed; |scale*s| small) ----
#pragma unroll
        for (int mt = 0; mt < 2; mt++) {
            float s0 = 0.f, s1 = 0.f;
#pragma unroll
            for (int n = 0; n < 8; n++) {
                accS[mt][n][0] = ex2(accS[mt][n][0] * C);
                accS[mt][n][1] = ex2(accS[mt][n][1] * C);
                accS[mt][n][2] = ex2(accS[mt][n][2] * C);
                accS[mt][n][3] = ex2(accS[mt][n][3] * C);
                s0 += accS[mt][n][0] + accS[mt][n][1];
                s1 += accS[mt][n][2] + accS[mt][n][3];
            }
            s0 += __shfl_xor_sync(0xffffffffu, s0, 1);
            s0 += __shfl_xor_sync(0xffffffffu, s0, 2);
            s1 += __shfl_xor_sync(0xffffffffu, s1, 1);
            s1 += __shfl_xor_sync(0xffffffffu, s1, 2);
            if (tig == 0) {
                red[(wm + 16 * mt + gid) * 2 + half] = s0;
                red[(wm + 16 * mt + gid + 8) * 2 + half] = s1;
            }
        }
        __syncthreads();

        // ---- normalize + write P hi/lo ----
#pragma unroll
        for (int mt = 0; mt < 2; mt++) {
            int v1 = wm + 16 * mt + gid;
            int v2 = v1 + 8;
            float r0 = 1.f / (red[v1 * 2] + red[v1 * 2 + 1]);
            float r1 = 1.f / (red[v2 * 2] + red[v2 * 2 + 1]);
#pragma unroll
            for (int n = 0; n < 8; n++) {
                unsigned coff = (unsigned)((wn + 8 * n + tig * 2) * 2);
                float p0 = accS[mt][n][0] * r0, p1 = accS[mt][n][1] * r0;
                float p2 = accS[mt][n][2] * r1, p3 = accS[mt][n][3] * r1;
                __nv_bfloat16 h0 = __float2bfloat16(p0), h1 = __float2bfloat16(p1);
                __nv_bfloat16 h2 = __float2bfloat16(p2), h3 = __float2bfloat16(p3);
                *(unsigned*)(smem + OFF_PH + v1 * PSTR + coff) = pack_bf16(p0, p1);
                *(unsigned*)(smem + OFF_PL + v1 * PSTR + coff) =
                    pack_bf16(p0 - __bfloat162float(h0), p1 - __bfloat162float(h1));
                *(unsigned*)(smem + OFF_PH + v2 * PSTR + coff) = pack_bf16(p2, p3);
                *(unsigned*)(smem + OFF_PL + v2 * PSTR + coff) =
                    pack_bf16(p2 - __bfloat162float(h2), p3 - __bfloat162float(h3));
            }
        }
        __syncthreads();

        // ---- O-GEMM: accO[4 ne][4] += P^T @ V ----
        {
            unsigned prow = (unsigned)(((lane & 16) >> 1) + (lane & 7));
            unsigned pcol = (unsigned)((lb + (lane & 8)) * 2);
            unsigned vrow = (unsigned)(lane & 15);
#pragma unroll
            for (int kv = 0; kv < 8; kv++) {
                unsigned aPh[4], aPl[4];
                unsigned poff = (16 * kv + prow) * PSTR + pcol;
                ldsm_x4_t(aPh, sb + OFF_PH + poff);
                ldsm_x4_t(aPl, sb + OFF_PL + poff);
                unsigned vbase = (16 * kv + vrow) * QSTR;
#pragma unroll
                for (int ne = 0; ne < 4; ne++) {
                    unsigned bh[2], bl[2];
                    unsigned voff = vbase + ne * 16;
                    ldsm_x2_t(bh, kvb + 20480 + voff);   // VH
                    ldsm_x2_t(bl, kvb + 30720 + voff);   // VL
                    mma16816(accO[ne], aPh, bh);
                    mma16816(accO[ne], aPh, bl);
                    mma16816(accO[ne], aPl, bh);
                }
            }
        }
        __syncthreads();
    }

    // ---- write split partials ----
    float* pout = part + (size_t)((b * HH + h) * SPLITS + s) * LL * EE;
#pragma unroll
    for (int ne = 0; ne < 4; ne++) {
        int e0 = ne * 8 + tig * 2;
        int l1 = lb + gid;
        *(float2*)(pout + l1 * EE + e0) = make_float2(accO[ne][0], accO[ne][1]);
        *(float2*)(pout + (l1 + 8) * EE + e0) = make_float2(accO[ne][2], accO[ne][3]);
    }
}

__global__ void reduce_part(const float* __restrict__ part, float* __restrict__ reprog)
{
    int t = blockIdx.x * blockDim.x + threadIdx.x;
    if (t >= BB * LL * DM) return;
    int e = t & 31;
    int h = (t >> 5) & 7;
    int l = (t >> 8) & 127;
    int b = t >> 15;
    const float* p = part + (size_t)(b * HH + h) * SPLITS * LL * EE + l * EE + e;
    float acc = 0.f;
#pragma unroll
    for (int s2 = 0; s2 < SPLITS; s2++) acc += p[(size_t)s2 * LL * EE];
    reprog[t] = acc;
}

// ============================================================
// Launch
// ============================================================
extern "C" void kernel_launch(void* const* d_in, const int* in_sizes, int n_in,
                              void* d_out, int out_size)
{
    (void)in_sizes; (void)n_in; (void)out_size;
    const float* ts = (const float*)d_in[0];
    const float* we = (const float*)d_in[1];
    const float* Wq = (const float*)d_in[2];
    const float* bq = (const float*)d_in[3];
    const float* Wk = (const float*)d_in[4];
    const float* bk = (const float*)d_in[5];
    const float* Wv = (const float*)d_in[6];
    const float* bv = (const float*)d_in[7];
    const float* Wo = (const float*)d_in[8];
    const float* bo = (const float*)d_in[9];
    float* out = (float*)d_out;

    float *gq, *gp, *gr;
    __nv_bfloat16 *ah, *al, *wkh, *wkl, *wvh, *wvl, *kh, *kl, *vh, *vl, *qh, *ql;
    cudaGetSymbolAddress((void**)&gq, g_query);
    cudaGetSymbolAddress((void**)&gp, g_part);
    cudaGetSymbolAddress((void**)&gr, g_reprog);
    cudaGetSymbolAddress((void**)&ah, g_Ah);
    cudaGetSymbolAddress((void**)&al, g_Al);
    cudaGetSymbolAddress((void**)&wkh, g_Wkh);
    cudaGetSymbolAddress((void**)&wkl, g_Wkl);
    cudaGetSymbolAddress((void**)&wvh, g_Wvh);
    cudaGetSymbolAddress((void**)&wvl, g_Wvl);
    cudaGetSymbolAddress((void**)&kh, g_Kh);
    cudaGetSymbolAddress((void**)&kl, g_Kl);
    cudaGetSymbolAddress((void**)&vh, g_Vh);
    cudaGetSymbolAddress((void**)&vl, g_Vl);
    cudaGetSymbolAddress((void**)&qh, g_Qh);
    cudaGetSymbolAddress((void**)&ql, g_Ql);

    cudaFuncSetAttribute(kv_gemm, cudaFuncAttributeMaxDynamicSharedMemorySize, KV_SMEM);
    cudaFuncSetAttribute(attn_tc, cudaFuncAttributeMaxDynamicSharedMemorySize, ATTN_SMEM);

    // conversions
    {
        size_t tot4 = (size_t)VPAD * DW / 4;
        conv_a<<<(unsigned)((tot4 + 255) / 256), 256>>>(we, ah, al);
        dim3 wb(32, 8);
        conv_w<<<dim3(DW / 32, DM / 32), wb>>>(Wk, wkh, wkl);
        conv_w<<<dim3(DW / 32, DM / 32), wb>>>(Wv, wvh, wvl);
    }
    // Q projection + bf16 split
    sgemm64<<<dim3(BB * LL / 64, DM / 64), 256>>>(ts, Wq, bq, gq, BB * LL, DM, DM);
    conv_q<<<(BB * LL * DM + 255) / 256, 256>>>(gq, qh, ql);
    // K / V projections -> bf16 hi/lo
    kv_gemm<<<VPAD / 128, 512, KV_SMEM>>>(ah, al, wkh, wkl, bk, kh, kl);
    kv_gemm<<<VPAD / 128, 512, KV_SMEM>>>(ah, al, wvh, wvl, bv, vh, vl);
    // tensor-core attention
    attn_tc<<<dim3(SPLITS, HH, BB), 256, ATTN_SMEM>>>(qh, ql, kh, kl, vh, vl, gp);
    reduce_part<<<(BB * LL * DM + 255) / 256, 256>>>(gp, gr);
    // output projection
    sgemm64<<<dim3(BB * LL / 64, DM / 64), 256>>>(gr, Wo, bo, out, BB * LL, DM, DM);
}

// round 5
// speedup vs baseline: 2.9602x; 1.0001x over previous
#include <cuda_runtime.h>
#include <cuda_bf16.h>

#define BB 4
#define LL 128
#define DM 256
#define VV 50257
#define VPAD 50304          /* 393 * 128 */
#define NTILE 393
#define DW 768
#define HH 8
#define EE 32
#define SPLITS 9

// ---- scratch (static device allocations; no cudaMalloc anywhere) ----
__device__ float g_query[BB * LL * DM];
__device__ float g_part[BB * HH * SPLITS * LL * EE];
__device__ float g_reprog[BB * LL * DM];
__device__ __nv_bfloat16 g_Ah[(size_t)VPAD * DW];
__device__ __nv_bfloat16 g_Al[(size_t)VPAD * DW];
__device__ __nv_bfloat16 g_Wkh[(size_t)DM * DW];
__device__ __nv_bfloat16 g_Wkl[(size_t)DM * DW];
__device__ __nv_bfloat16 g_Wvh[(size_t)DM * DW];
__device__ __nv_bfloat16 g_Wvl[(size_t)DM * DW];
__device__ __nv_bfloat16 g_Kh[(size_t)VPAD * DM];
__device__ __nv_bfloat16 g_Kl[(size_t)VPAD * DM];
__device__ __nv_bfloat16 g_Vh[(size_t)VPAD * DM];
__device__ __nv_bfloat16 g_Vl[(size_t)VPAD * DM];
__device__ __nv_bfloat16 g_Qh[BB * LL * DM];
__device__ __nv_bfloat16 g_Ql[BB * LL * DM];

// ============================================================
// portable PTX helpers (sm_80-level; no sm_103a-only ISA)
// ============================================================
__device__ __forceinline__ unsigned smem_u32(const void* p) {
    unsigned a;
    asm("{ .reg .u64 t; cvta.to.shared.u64 t, %1; cvt.u32.u64 %0, t; }" : "=r"(a) : "l"(p));
    return a;
}
__device__ __forceinline__ void cp_async16(unsigned dst, const void* src) {
    asm volatile("cp.async.cg.shared.global [%0], [%1], 16;" :: "r"(dst), "l"(src));
}
#define CP_COMMIT() asm volatile("cp.async.commit_group;" ::: "memory")
#define CP_WAIT(n)  asm volatile("cp.async.wait_group %0;" :: "n"(n) : "memory")

__device__ __forceinline__ void ldsm_x4(unsigned* r, unsigned addr) {
    asm volatile("ldmatrix.sync.aligned.m8n8.x4.shared.b16 {%0,%1,%2,%3}, [%4];"
                 : "=r"(r[0]), "=r"(r[1]), "=r"(r[2]), "=r"(r[3]) : "r"(addr));
}
__device__ __forceinline__ void ldsm_x2(unsigned* r, unsigned addr) {
    asm volatile("ldmatrix.sync.aligned.m8n8.x2.shared.b16 {%0,%1}, [%2];"
                 : "=r"(r[0]), "=r"(r[1]) : "r"(addr));
}
__device__ __forceinline__ void ldsm_x4_t(unsigned* r, unsigned addr) {
    asm volatile("ldmatrix.sync.aligned.m8n8.x4.trans.shared.b16 {%0,%1,%2,%3}, [%4];"
                 : "=r"(r[0]), "=r"(r[1]), "=r"(r[2]), "=r"(r[3]) : "r"(addr));
}
__device__ __forceinline__ void ldsm_x2_t(unsigned* r, unsigned addr) {
    asm volatile("ldmatrix.sync.aligned.m8n8.x2.trans.shared.b16 {%0,%1}, [%2];"
                 : "=r"(r[0]), "=r"(r[1]) : "r"(addr));
}
__device__ __forceinline__ void mma16816(float* c, const unsigned* a, const unsigned* b) {
    asm volatile("mma.sync.aligned.m16n8k16.row.col.f32.bf16.bf16.f32 "
                 "{%0,%1,%2,%3}, {%4,%5,%6,%7}, {%8,%9}, {%0,%1,%2,%3};"
                 : "+f"(c[0]), "+f"(c[1]), "+f"(c[2]), "+f"(c[3])
                 : "r"(a[0]), "r"(a[1]), "r"(a[2]), "r"(a[3]), "r"(b[0]), "r"(b[1]));
}
__device__ __forceinline__ float ex2(float x) {
    float r;
    asm("ex2.approx.ftz.f32 %0, %1;" : "=f"(r) : "f"(x));
    return r;
}
__device__ __forceinline__ unsigned pack_bf16(float a, float b) {
    __nv_bfloat162 t(__float2bfloat16(a), __float2bfloat16(b));
    return *(unsigned*)&t;
}

// ============================================================
// conversion kernels: fp32 -> bf16 hi/lo split
// ============================================================
__global__ void conv_a(const float* __restrict__ A, __nv_bfloat16* __restrict__ Ah,
                       __nv_bfloat16* __restrict__ Al)
{
    size_t i4 = (size_t)blockIdx.x * blockDim.x + threadIdx.x;
    size_t total = (size_t)VPAD * DW / 4;
    if (i4 >= total) return;
    size_t off = i4 * 4;
    size_t row = off / DW;
    float4 v = make_float4(0.f, 0.f, 0.f, 0.f);
    if (row < VV) v = *(const float4*)(A + off);
    float vv[4] = {v.x, v.y, v.z, v.w};
    __nv_bfloat16 h[4], l[4];
#pragma unroll
    for (int j = 0; j < 4; j++) {
        h[j] = __float2bfloat16(vv[j]);
        l[j] = __float2bfloat16(vv[j] - __bfloat162float(h[j]));
    }
    *(__nv_bfloat162*)(Ah + off)     = __nv_bfloat162(h[0], h[1]);
    *(__nv_bfloat162*)(Ah + off + 2) = __nv_bfloat162(h[2], h[3]);
    *(__nv_bfloat162*)(Al + off)     = __nv_bfloat162(l[0], l[1]);
    *(__nv_bfloat162*)(Al + off + 2) = __nv_bfloat162(l[2], l[3]);
}

__global__ void conv_w(const float* __restrict__ W, __nv_bfloat16* __restrict__ Wh,
                       __nv_bfloat16* __restrict__ Wl)
{
    __shared__ float tile[32][33];
    int k0 = blockIdx.x * 32, n0 = blockIdx.y * 32;
    int tx = threadIdx.x, ty = threadIdx.y;
    for (int r = ty; r < 32; r += 8)
        tile[r][tx] = W[(size_t)(k0 + r) * DM + n0 + tx];
    __syncthreads();
    for (int r = ty; r < 32; r += 8) {
        float v = tile[tx][r];
        __nv_bfloat16 h = __float2bfloat16(v);
        __nv_bfloat16 l = __float2bfloat16(v - __bfloat162float(h));
        Wh[(size_t)(n0 + r) * DW + k0 + tx] = h;
        Wl[(size_t)(n0 + r) * DW + k0 + tx] = l;
    }
}

__global__ void conv_q(const float* __restrict__ Q, __nv_bfloat16* __restrict__ Qh,
                       __nv_bfloat16* __restrict__ Ql)
{
    int i = blockIdx.x * blockDim.x + threadIdx.x;
    if (i >= BB * LL * DM) return;
    float v = Q[i];
    __nv_bfloat16 h = __float2bfloat16(v);
    Qh[i] = h;
    Ql[i] = __float2bfloat16(v - __bfloat162float(h));
}

// ============================================================
// mma.sync bf16 projection GEMM (3-term split), bf16 hi/lo output
// ============================================================
#define BK 32
#define ASTR 80
#define STG_AH 0
#define STG_AL (128 * ASTR)
#define STG_WH (2 * 128 * ASTR)
#define STG_WL (STG_WH + 256 * ASTR)
#define STG_SZ (STG_WL + 256 * ASTR)
#define KV_SMEM (2 * STG_SZ)
#define NCH (DW / BK)

__global__ void __launch_bounds__(512, 1)
kv_gemm(const __nv_bfloat16* __restrict__ Ah, const __nv_bfloat16* __restrict__ Al,
        const __nv_bfloat16* __restrict__ Wh, const __nv_bfloat16* __restrict__ Wl,
        const float* __restrict__ bias,
        __nv_bfloat16* __restrict__ outH, __nv_bfloat16* __restrict__ outL)
{
    extern __shared__ char smem[];
    unsigned sb = smem_u32(smem);
    int t = threadIdx.x, lane = t & 31, wid = t >> 5;
    int mBase = blockIdx.x * 128;
    int wm = (wid & 1) * 64;
    int wn = (wid >> 1) * 32;

    float acc[4][4][4];
#pragma unroll
    for (int i = 0; i < 4; i++)
#pragma unroll
        for (int j = 0; j < 4; j++)
#pragma unroll
            for (int k = 0; k < 4; k++) acc[i][j][k] = 0.f;

    unsigned a_lof = (unsigned)((lane & 15) * ASTR + (lane >> 4) * 16);
    int l2 = lane & 15;
    unsigned w_lof = (unsigned)((l2 & 7) * ASTR + (l2 >> 3) * 16);

    auto load_stage = [&](int s, int k0) {
        unsigned stg = sb + s * STG_SZ;
        {
            int row = t >> 2, ch = t & 3;
            size_t go = (size_t)(mBase + row) * DW + k0 + ch * 8;
            unsigned d = stg + STG_AH + row * ASTR + ch * 16;
            cp_async16(d, Ah + go);
            cp_async16(d + (STG_AL - STG_AH), Al + go);
        }
#pragma unroll
        for (int r2 = 0; r2 < 2; r2++) {
            int i = t + r2 * 512;
            int row = i >> 2, ch = i & 3;
            size_t go = (size_t)row * DW + k0 + ch * 8;
            unsigned d = stg + STG_WH + row * ASTR + ch * 16;
            cp_async16(d, Wh + go);
            cp_async16(d + (STG_WL - STG_WH), Wl + go);
        }
    };

    load_stage(0, 0);
    CP_COMMIT();

    for (int c = 0; c < NCH; c++) {
        if (c + 1 < NCH) {
            load_stage((c + 1) & 1, (c + 1) * BK);
            CP_COMMIT();
            CP_WAIT(1);
        } else {
            CP_WAIT(0);
        }
        __syncthreads();

        unsigned stg = sb + (c & 1) * STG_SZ;
        unsigned aH = stg + STG_AH + wm * ASTR + a_lof;
        unsigned aL = stg + STG_AL + wm * ASTR + a_lof;
        unsigned wH = stg + STG_WH + wn * ASTR + w_lof;
        unsigned wL = stg + STG_WL + wn * ASTR + w_lof;

#pragma unroll
        for (int ks = 0; ks < 2; ks++) {
            unsigned kb = ks * 32;
            unsigned a[4][4], bh[4][2], bl[4][2];
#pragma unroll
            for (int mt = 0; mt < 4; mt++) ldsm_x4(a[mt], aH + mt * (16 * ASTR) + kb);
#pragma unroll
            for (int nt = 0; nt < 4; nt++) {
                ldsm_x2(bh[nt], wH + nt * (8 * ASTR) + kb);
                ldsm_x2(bl[nt], wL + nt * (8 * ASTR) + kb);
            }
#pragma unroll
            for (int mt = 0; mt < 4; mt++)
#pragma unroll
                for (int nt = 0; nt < 4; nt++) mma16816(acc[mt][nt], a[mt], bh[nt]);
#pragma unroll
            for (int mt = 0; mt < 4; mt++)
#pragma unroll
                for (int nt = 0; nt < 4; nt++) mma16816(acc[mt][nt], a[mt], bl[nt]);
#pragma unroll
            for (int mt = 0; mt < 4; mt++) ldsm_x4(a[mt], aL + mt * (16 * ASTR) + kb);
#pragma unroll
            for (int mt = 0; mt < 4; mt++)
#pragma unroll
                for (int nt = 0; nt < 4; nt++) mma16816(acc[mt][nt], a[mt], bh[nt]);
        }
        __syncthreads();
    }

    // epilogue: bf16 hi/lo output, zero padded rows
    int gid = lane >> 2, tig = lane & 3;
#pragma unroll
    for (int nt = 0; nt < 4; nt++) {
        int col = wn + nt * 8 + tig * 2;
        float2 bv = *(const float2*)(bias + col);
#pragma unroll
        for (int mt = 0; mt < 4; mt++) {
            int r0 = mBase + wm + mt * 16 + gid;
            int r1 = r0 + 8;
            float x0 = (r0 < VV) ? acc[mt][nt][0] + bv.x : 0.f;
            float x1 = (r0 < VV) ? acc[mt][nt][1] + bv.y : 0.f;
            float x2 = (r1 < VV) ? acc[mt][nt][2] + bv.x : 0.f;
            float x3 = (r1 < VV) ? acc[mt][nt][3] + bv.y : 0.f;
            __nv_bfloat16 h0 = __float2bfloat16(x0), h1 = __float2bfloat16(x1);
            __nv_bfloat16 h2 = __float2bfloat16(x2), h3 = __float2bfloat16(x3);
            *(unsigned*)(outH + (size_t)r0 * DM + col) = pack_bf16(x0, x1);
            *(unsigned*)(outL + (size_t)r0 * DM + col) =
                pack_bf16(x0 - __bfloat162float(h0), x1 - __bfloat162float(h1));
            *(unsigned*)(outH + (size_t)r1 * DM + col) = pack_bf16(x2, x3);
            *(unsigned*)(outL + (size_t)r1 * DM + col) =
                pack_bf16(x2 - __bfloat162float(h2), x3 - __bfloat162float(h3));
        }
    }
}

// ============================================================
// small fp32 SGEMM 64x64 tiles (Q / O projections)
// ============================================================
__global__ __launch_bounds__(256) void sgemm64(
    const float* __restrict__ A, const float* __restrict__ Bw,
    const float* __restrict__ bias, float* __restrict__ C,
    int M, int N, int K)
{
    __shared__ float As[16][68];
    __shared__ float Bs[16][68];
    int t = threadIdx.x, tx = t & 15, ty = t >> 4;
    int mB = blockIdx.x * 64, nB = blockIdx.y * 64;
    float acc[4][4];
#pragma unroll
    for (int i = 0; i < 4; i++)
#pragma unroll
        for (int j = 0; j < 4; j++) acc[i][j] = 0.f;

    for (int k0 = 0; k0 < K; k0 += 16) {
        {
            int row = t >> 2, kk = (t & 3) * 4;
            float4 av = *(const float4*)(A + (size_t)(mB + row) * K + k0 + kk);
            As[kk + 0][row] = av.x; As[kk + 1][row] = av.y;
            As[kk + 2][row] = av.z; As[kk + 3][row] = av.w;
        }
        {
            int kr = t >> 4, c4 = (t & 15) * 4;
            *(float4*)&Bs[kr][c4] = *(const float4*)(Bw + (size_t)(k0 + kr) * N + nB + c4);
        }
        __syncthreads();
#pragma unroll
        for (int kk = 0; kk < 16; kk++) {
            float4 a = *(const float4*)&As[kk][ty * 4];
            float4 b = *(const float4*)&Bs[kk][tx * 4];
            float am[4] = {a.x, a.y, a.z, a.w};
            float bn[4] = {b.x, b.y, b.z, b.w};
#pragma unroll
            for (int i = 0; i < 4; i++)
#pragma unroll
                for (int j = 0; j < 4; j++) acc[i][j] += am[i] * bn[j];
        }
        __syncthreads();
    }
#pragma unroll
    for (int i = 0; i < 4; i++) {
        int m = mB + ty * 4 + i;
#pragma unroll
        for (int j = 0; j < 4; j++) {
            int n = nB + tx * 4 + j;
            C[(size_t)m * N + n] = acc[i][j] + bias[n];
        }
    }
}

// ============================================================
// Tensor-core fused attention
// CTA = (split s, head h, batch b); 8 warps, 256 threads.
// Per 128-v tile:  S = K Q^T (3-term) -> softmax over l -> P hi/lo
//                  O += P^T V (3-term), partials to g_part.
// ============================================================
#define QSTR 80
#define PSTR 272
#define OFF_QH 0
#define OFF_QL 10240
#define OFF_KV 20480
#define KVBUF 40960         /* KH,KL,VH,VL each 10240 */
#define OFF_PH (20480 + 2 * KVBUF)          /* 102400 */
#define OFF_PL (OFF_PH + 128 * PSTR)        /* 137216 */
#define OFF_RED (OFF_PL + 128 * PSTR)       /* 172032 */
#define ATTN_SMEM (OFF_RED + 1024)          /* 173056 */

__global__ void __launch_bounds__(256, 1)
attn_tc(const __nv_bfloat16* __restrict__ Qh, const __nv_bfloat16* __restrict__ Ql,
        const __nv_bfloat16* __restrict__ Kh, const __nv_bfloat16* __restrict__ Kl,
        const __nv_bfloat16* __restrict__ Vh, const __nv_bfloat16* __restrict__ Vl,
        float* __restrict__ part)
{
    extern __shared__ char smem[];
    unsigned sb = smem_u32(smem);
    float* red = (float*)(smem + OFF_RED);

    int t = threadIdx.x, lane = t & 31, wid = t >> 5;
    int s = blockIdx.x, h = blockIdx.y, b = blockIdx.z;
    int gid = lane >> 2, tig = lane & 3;

    int wm = (wid & 3) * 32;       // S-phase: v rows
    int wn = (wid >> 2) * 64;      // S-phase: l cols
    int half = wid >> 2;
    int lb = wid * 16;             // O-phase: l rows

    // ---- load Q slice [128 l][32 e] hi/lo into smem ----
    {
        size_t qbase = (size_t)(b * LL) * DM + h * EE;
#pragma unroll
        for (int j = 0; j < 2; j++) {
            int idx = t + j * 256;          // 0..511
            int row = idx >> 2, c = idx & 3;
            size_t go = qbase + (size_t)row * DM + c * 8;
            unsigned d = sb + row * QSTR + c * 16;
            cp_async16(d + OFF_QH, Qh + go);
            cp_async16(d + OFF_QL, Ql + go);
        }
    }
    CP_COMMIT();
    CP_WAIT(0);
    __syncthreads();

    // ---- Q B-fragments in registers (per warp: its 64 l-cols) ----
    unsigned qhf[8][2][2], qlf[8][2][2];
    {
        int l15 = lane & 15;
        unsigned base = (unsigned)((l15 & 7) * QSTR + ((l15 >> 3) * 16));
#pragma unroll
        for (int n = 0; n < 8; n++)
#pragma unroll
            for (int k = 0; k < 2; k++) {
                unsigned off = (wn + 8 * n) * QSTR + base + k * 32;
                ldsm_x2(qhf[n][k], sb + OFF_QH + off);
                ldsm_x2(qlf[n][k], sb + OFF_QL + off);
            }
    }

    float accO[4][4];
#pragma unroll
    for (int i = 0; i < 4; i++)
#pragma unroll
        for (int j = 0; j < 4; j++) accO[i][j] = 0.f;

    // tiles for this split
    int tile0 = s;
    size_t hof = (size_t)h * EE;

    auto load_kv = [&](int buf, int v0) {
        unsigned base = sb + OFF_KV + buf * KVBUF;
#pragma unroll
        for (int j = 0; j < 2; j++) {
            int idx = t + j * 256;
            int row = idx >> 2, c = idx & 3;
            size_t go = (size_t)(v0 + row) * DM + hof + c * 8;
            unsigned d = base + row * QSTR + c * 16;
            cp_async16(d,             Kh + go);
            cp_async16(d + 10240,     Kl + go);
            cp_async16(d + 20480,     Vh + go);
            cp_async16(d + 30720,     Vl + go);
        }
    };

    load_kv(0, tile0 * 128);
    CP_COMMIT();

    const float C = 0.25503327723425473f;  // scale * log2(e)

    int it = 0;
    for (int tile = tile0; tile < NTILE; tile += SPLITS, it++) {
        int nxt = tile + SPLITS;
        if (nxt < NTILE) {
            load_kv((it + 1) & 1, nxt * 128);
            CP_COMMIT();
            CP_WAIT(1);
        } else {
            CP_WAIT(0);
        }
        __syncthreads();

        unsigned kvb = sb + OFF_KV + (it & 1) * KVBUF;

        // ---- S-GEMM: accS[2 mt][8 n][4] ----
        float accS[2][8][4];
#pragma unroll
        for (int mt = 0; mt < 2; mt++)
#pragma unroll
            for (int n = 0; n < 8; n++)
#pragma unroll
                for (int q = 0; q < 4; q++) accS[mt][n][q] = 0.f;

        {
            unsigned alof = (unsigned)((lane & 15) * QSTR + (lane >> 4) * 16);
            unsigned aH[2][2][4], aL[2][2][4];
#pragma unroll
            for (int mt = 0; mt < 2; mt++)
#pragma unroll
                for (int k = 0; k < 2; k++) {
                    unsigned off = (wm + 16 * mt) * QSTR + alof + k * 32;
                    ldsm_x4(aH[mt][k], kvb + off);            // KH
                    ldsm_x4(aL[mt][k], kvb + 10240 + off);    // KL
                }
#pragma unroll
            for (int mt = 0; mt < 2; mt++)
#pragma unroll
                for (int n = 0; n < 8; n++)
#pragma unroll
                    for (int k = 0; k < 2; k++) {
                        mma16816(accS[mt][n], aH[mt][k], qhf[n][k]);
                        mma16816(accS[mt][n], aH[mt][k], qlf[n][k]);
                        mma16816(accS[mt][n], aL[mt][k], qhf[n][k]);
                    }
        }

        // ---- exp + partial row sums (no max-sub needed; |scale*s| small) ----
#pragma unroll
        for (int mt = 0; mt < 2; mt++) {
            float s0 = 0.f, s1 = 0.f;
#pragma unroll
            for (int n = 0; n < 8; n++) {
                accS[mt][n][0] = ex2(accS[mt][n][0] * C);
                accS[mt][n][1] = ex2(accS[mt][n][1] * C);
                accS[mt][n][2] = ex2(accS[mt][n][2] * C);
                accS[mt][n][3] = ex2(accS[mt][n][3] * C);
                s0 += accS[mt][n][0] + accS[mt][n][1];
                s1 += accS[mt][n][2] + accS[mt][n][3];
            }
            s0 += __shfl_xor_sync(0xffffffffu, s0, 1);
            s0 += __shfl_xor_sync(0xffffffffu, s0, 2);
            s1 += __shfl_xor_sync(0xffffffffu, s1, 1);
            s1 += __shfl_xor_sync(0xffffffffu, s1, 2);
            if (tig == 0) {
                red[(wm + 16 * mt + gid) * 2 + half] = s0;
                red[(wm + 16 * mt + gid + 8) * 2 + half] = s1;
            }
        }
        __syncthreads();

        // ---- normalize + write P hi/lo ----
#pragma unroll
        for (int mt = 0; mt < 2; mt++) {
            int v1 = wm + 16 * mt + gid;
            int v2 = v1 + 8;
            float r0 = 1.f / (red[v1 * 2] + red[v1 * 2 + 1]);
            float r1 = 1.f / (red[v2 * 2] + red[v2 * 2 + 1]);
#pragma unroll
            for (int n = 0; n < 8; n++) {
                unsigned coff = (unsigned)((wn + 8 * n + tig * 2) * 2);
                float p0 = accS[mt][n][0] * r0, p1 = accS[mt][n][1] * r0;
                float p2 = accS[mt][n][2] * r1, p3 = accS[mt][n][3] * r1;
                __nv_bfloat16 h0 = __float2bfloat16(p0), h1 = __float2bfloat16(p1);
                __nv_bfloat16 h2 = __float2bfloat16(p2), h3 = __float2bfloat16(p3);
                *(unsigned*)(smem + OFF_PH + v1 * PSTR + coff) = pack_bf16(p0, p1);
                *(unsigned*)(smem + OFF_PL + v1 * PSTR + coff) =
                    pack_bf16(p0 - __bfloat162float(h0), p1 - __bfloat162float(h1));
                *(unsigned*)(smem + OFF_PH + v2 * PSTR + coff) = pack_bf16(p2, p3);
                *(unsigned*)(smem + OFF_PL + v2 * PSTR + coff) =
                    pack_bf16(p2 - __bfloat162float(h2), p3 - __bfloat162float(h3));
            }
        }
        __syncthreads();

        // ---- O-GEMM: accO[4 ne][4] += P^T @ V ----
        {
            unsigned prow = (unsigned)(((lane & 16) >> 1) + (lane & 7));
            unsigned pcol = (unsigned)((lb + (lane & 8)) * 2);
            unsigned vrow = (unsigned)(lane & 15);
#pragma unroll
            for (int kv = 0; kv < 8; kv++) {
                unsigned aPh[4], aPl[4];
                unsigned poff = (16 * kv + prow) * PSTR + pcol;
                ldsm_x4_t(aPh, sb + OFF_PH + poff);
                ldsm_x4_t(aPl, sb + OFF_PL + poff);
                unsigned vbase = (16 * kv + vrow) * QSTR;
#pragma unroll
                for (int ne = 0; ne < 4; ne++) {
                    unsigned bh[2], bl[2];
                    unsigned voff = vbase + ne * 16;
                    ldsm_x2_t(bh, kvb + 20480 + voff);   // VH
                    ldsm_x2_t(bl, kvb + 30720 + voff);   // VL
                    mma16816(accO[ne], aPh, bh);
                    mma16816(accO[ne], aPh, bl);
                    mma16816(accO[ne], aPl, bh);
                }
            }
        }
        __syncthreads();
    }

    // ---- write split partials ----
    float* pout = part + (size_t)((b * HH + h) * SPLITS + s) * LL * EE;
#pragma unroll
    for (int ne = 0; ne < 4; ne++) {
        int e0 = ne * 8 + tig * 2;
        int l1 = lb + gid;
        *(float2*)(pout + l1 * EE + e0) = make_float2(accO[ne][0], accO[ne][1]);
        *(float2*)(pout + (l1 + 8) * EE + e0) = make_float2(accO[ne][2], accO[ne][3]);
    }
}

__global__ void reduce_part(const float* __restrict__ part, float* __restrict__ reprog)
{
    int t = blockIdx.x * blockDim.x + threadIdx.x;
    if (t >= BB * LL * DM) return;
    int e = t & 31;
    int h = (t >> 5) & 7;
    int l = (t >> 8) & 127;
    int b = t >> 15;
    const float* p = part + (size_t)(b * HH + h) * SPLITS * LL * EE + l * EE + e;
    float acc = 0.f;
#pragma unroll
    for (int s2 = 0; s2 < SPLITS; s2++) acc += p[(size_t)s2 * LL * EE];
    reprog[t] = acc;
}

// ============================================================
// Launch
// ============================================================
extern "C" void kernel_launch(void* const* d_in, const int* in_sizes, int n_in,
                              void* d_out, int out_size)
{
    (void)in_sizes; (void)n_in; (void)out_size;
    const float* ts = (const float*)d_in[0];
    const float* we = (const float*)d_in[1];
    const float* Wq = (const float*)d_in[2];
    const float* bq = (const float*)d_in[3];
    const float* Wk = (const float*)d_in[4];
    const float* bk = (const float*)d_in[5];
    const float* Wv = (const float*)d_in[6];
    const float* bv = (const float*)d_in[7];
    const float* Wo = (const float*)d_in[8];
    const float* bo = (const float*)d_in[9];
    float* out = (float*)d_out;

    float *gq, *gp, *gr;
    __nv_bfloat16 *ah, *al, *wkh, *wkl, *wvh, *wvl, *kh, *kl, *vh, *vl, *qh, *ql;
    cudaGetSymbolAddress((void**)&gq, g_query);
    cudaGetSymbolAddress((void**)&gp, g_part);
    cudaGetSymbolAddress((void**)&gr, g_reprog);
    cudaGetSymbolAddress((void**)&ah, g_Ah);
    cudaGetSymbolAddress((void**)&al, g_Al);
    cudaGetSymbolAddress((void**)&wkh, g_Wkh);
    cudaGetSymbolAddress((void**)&wkl, g_Wkl);
    cudaGetSymbolAddress((void**)&wvh, g_Wvh);
    cudaGetSymbolAddress((void**)&wvl, g_Wvl);
    cudaGetSymbolAddress((void**)&kh, g_Kh);
    cudaGetSymbolAddress((void**)&kl, g_Kl);
    cudaGetSymbolAddress((void**)&vh, g_Vh);
    cudaGetSymbolAddress((void**)&vl, g_Vl);
    cudaGetSymbolAddress((void**)&qh, g_Qh);
    cudaGetSymbolAddress((void**)&ql, g_Ql);

    cudaFuncSetAttribute(kv_gemm, cudaFuncAttributeMaxDynamicSharedMemorySize, KV_SMEM);
    cudaFuncSetAttribute(attn_tc, cudaFuncAttributeMaxDynamicSharedMemorySize, ATTN_SMEM);

    // conversions
    {
        size_t tot4 = (size_t)VPAD * DW / 4;
        conv_a<<<(unsigned)((tot4 + 255) / 256), 256>>>(we, ah, al);
        dim3 wb(32, 8);
        conv_w<<<dim3(DW / 32, DM / 32), wb>>>(Wk, wkh, wkl);
        conv_w<<<dim3(DW / 32, DM / 32), wb>>>(Wv, wvh, wvl);
    }
    // Q projection + bf16 split
    sgemm64<<<dim3(BB * LL / 64, DM / 64), 256>>>(ts, Wq, bq, gq, BB * LL, DM, DM);
    conv_q<<<(BB * LL * DM + 255) / 256, 256>>>(gq, qh, ql);
    // K / V projections -> bf16 hi/lo
    kv_gemm<<<VPAD / 128, 512, KV_SMEM>>>(ah, al, wkh, wkl, bk, kh, kl);
    kv_gemm<<<VPAD / 128, 512, KV_SMEM>>>(ah, al, wvh, wvl, bv, vh, vl);
    // tensor-core attention
    attn_tc<<<dim3(SPLITS, HH, BB), 256, ATTN_SMEM>>>(qh, ql, kh, kl, vh, vl, gp);
    reduce_part<<<(BB * LL * DM + 255) / 256, 256>>>(gp, gr);
    // output projection
    sgemm64<<<dim3(BB * LL / 64, DM / 64), 256>>>(gr, Wo, bo, out, BB * LL, DM, DM);
}

// round 6
// speedup vs baseline: 3.0444x; 1.0285x over previous
#include <cuda_runtime.h>
#include <cuda_bf16.h>

#define BB 4
#define LL 128
#define DM 256
#define VV 50257
#define VPAD 50304          /* 393 * 128 */
#define NTILE 393
#define DW 768
#define HH 8
#define EE 32
#define SPLITS 9
#define SPL4 (SPLITS * 4)

// ---- scratch (static device allocations; no cudaMalloc anywhere) ----
__device__ float g_query[BB * LL * DM];
__device__ float g_part[BB * HH * SPL4 * LL * EE];
__device__ float g_reprog[BB * LL * DM];
__device__ float g_sg[4 * BB * LL * DM];
__device__ __nv_bfloat16 g_Ah[(size_t)VPAD * DW];
__device__ __nv_bfloat16 g_Al[(size_t)VPAD * DW];
__device__ __nv_bfloat16 g_Wkh[(size_t)DM * DW];
__device__ __nv_bfloat16 g_Wkl[(size_t)DM * DW];
__device__ __nv_bfloat16 g_Wvh[(size_t)DM * DW];
__device__ __nv_bfloat16 g_Wvl[(size_t)DM * DW];
__device__ __nv_bfloat16 g_Kh[(size_t)VPAD * DM];
__device__ __nv_bfloat16 g_Kl[(size_t)VPAD * DM];
__device__ __nv_bfloat16 g_Vh[(size_t)VPAD * DM];
__device__ __nv_bfloat16 g_Vl[(size_t)VPAD * DM];
__device__ __nv_bfloat16 g_Qh[BB * LL * DM];
__device__ __nv_bfloat16 g_Ql[BB * LL * DM];

// ============================================================
// portable PTX helpers
// ============================================================
__device__ __forceinline__ unsigned smem_u32(const void* p) {
    unsigned a;
    asm("{ .reg .u64 t; cvta.to.shared.u64 t, %1; cvt.u32.u64 %0, t; }" : "=r"(a) : "l"(p));
    return a;
}
__device__ __forceinline__ void cp_async16(unsigned dst, const void* src) {
    asm volatile("cp.async.cg.shared.global [%0], [%1], 16;" :: "r"(dst), "l"(src));
}
#define CP_COMMIT() asm volatile("cp.async.commit_group;" ::: "memory")
#define CP_WAIT(n)  asm volatile("cp.async.wait_group %0;" :: "n"(n) : "memory")

__device__ __forceinline__ void ldsm_x4(unsigned* r, unsigned addr) {
    asm volatile("ldmatrix.sync.aligned.m8n8.x4.shared.b16 {%0,%1,%2,%3}, [%4];"
                 : "=r"(r[0]), "=r"(r[1]), "=r"(r[2]), "=r"(r[3]) : "r"(addr));
}
__device__ __forceinline__ void ldsm_x2(unsigned* r, unsigned addr) {
    asm volatile("ldmatrix.sync.aligned.m8n8.x2.shared.b16 {%0,%1}, [%2];"
                 : "=r"(r[0]), "=r"(r[1]) : "r"(addr));
}
__device__ __forceinline__ void ldsm_x2_t(unsigned* r, unsigned addr) {
    asm volatile("ldmatrix.sync.aligned.m8n8.x2.trans.shared.b16 {%0,%1}, [%2];"
                 : "=r"(r[0]), "=r"(r[1]) : "r"(addr));
}
__device__ __forceinline__ void mma16816(float* c, const unsigned* a, const unsigned* b) {
    asm volatile("mma.sync.aligned.m16n8k16.row.col.f32.bf16.bf16.f32 "
                 "{%0,%1,%2,%3}, {%4,%5,%6,%7}, {%8,%9}, {%0,%1,%2,%3};"
                 : "+f"(c[0]), "+f"(c[1]), "+f"(c[2]), "+f"(c[3])
                 : "r"(a[0]), "r"(a[1]), "r"(a[2]), "r"(a[3]), "r"(b[0]), "r"(b[1]));
}
__device__ __forceinline__ float ex2(float x) {
    float r;
    asm("ex2.approx.ftz.f32 %0, %1;" : "=f"(r) : "f"(x));
    return r;
}
__device__ __forceinline__ unsigned pack_bf16(float a, float b) {
    __nv_bfloat162 t(__float2bfloat16(a), __float2bfloat16(b));
    return *(unsigned*)&t;
}

// ============================================================
// conversion kernels
// ============================================================
__global__ void conv_a(const float* __restrict__ A, __nv_bfloat16* __restrict__ Ah,
                       __nv_bfloat16* __restrict__ Al)
{
    size_t i4 = (size_t)blockIdx.x * blockDim.x + threadIdx.x;
    size_t total = (size_t)VPAD * DW / 4;
    if (i4 >= total) return;
    size_t off = i4 * 4;
    size_t row = off / DW;
    float4 v = make_float4(0.f, 0.f, 0.f, 0.f);
    if (row < VV) v = *(const float4*)(A + off);
    float vv[4] = {v.x, v.y, v.z, v.w};
    __nv_bfloat16 h[4], l[4];
#pragma unroll
    for (int j = 0; j < 4; j++) {
        h[j] = __float2bfloat16(vv[j]);
        l[j] = __float2bfloat16(vv[j] - __bfloat162float(h[j]));
    }
    *(__nv_bfloat162*)(Ah + off)     = __nv_bfloat162(h[0], h[1]);
    *(__nv_bfloat162*)(Ah + off + 2) = __nv_bfloat162(h[2], h[3]);
    *(__nv_bfloat162*)(Al + off)     = __nv_bfloat162(l[0], l[1]);
    *(__nv_bfloat162*)(Al + off + 2) = __nv_bfloat162(l[2], l[3]);
}

__global__ void conv_w(const float* __restrict__ W, __nv_bfloat16* __restrict__ Wh,
                       __nv_bfloat16* __restrict__ Wl)
{
    __shared__ float tile[32][33];
    int k0 = blockIdx.x * 32, n0 = blockIdx.y * 32;
    int tx = threadIdx.x, ty = threadIdx.y;
    for (int r = ty; r < 32; r += 8)
        tile[r][tx] = W[(size_t)(k0 + r) * DM + n0 + tx];
    __syncthreads();
    for (int r = ty; r < 32; r += 8) {
        float v = tile[tx][r];
        __nv_bfloat16 h = __float2bfloat16(v);
        __nv_bfloat16 l = __float2bfloat16(v - __bfloat162float(h));
        Wh[(size_t)(n0 + r) * DW + k0 + tx] = h;
        Wl[(size_t)(n0 + r) * DW + k0 + tx] = l;
    }
}

__global__ void conv_q(const float* __restrict__ Q, __nv_bfloat16* __restrict__ Qh,
                       __nv_bfloat16* __restrict__ Ql)
{
    int i = blockIdx.x * blockDim.x + threadIdx.x;
    if (i >= BB * LL * DM) return;
    float v = Q[i];
    __nv_bfloat16 h = __float2bfloat16(v);
    Qh[i] = h;
    Ql[i] = __float2bfloat16(v - __bfloat162float(h));
}

// ============================================================
// mma.sync bf16 projection GEMM (3-term split), bf16 hi/lo output
// ============================================================
#define BK 32
#define ASTR 80
#define STG_AH 0
#define STG_AL (128 * ASTR)
#define STG_WH (2 * 128 * ASTR)
#define STG_WL (STG_WH + 256 * ASTR)
#define STG_SZ (STG_WL + 256 * ASTR)
#define KV_SMEM (2 * STG_SZ)
#define NCH (DW / BK)

__global__ void __launch_bounds__(512, 1)
kv_gemm(const __nv_bfloat16* __restrict__ Ah, const __nv_bfloat16* __restrict__ Al,
        const __nv_bfloat16* __restrict__ Wh, const __nv_bfloat16* __restrict__ Wl,
        const float* __restrict__ bias,
        __nv_bfloat16* __restrict__ outH, __nv_bfloat16* __restrict__ outL)
{
    extern __shared__ char smem[];
    unsigned sb = smem_u32(smem);
    int t = threadIdx.x, lane = t & 31, wid = t >> 5;
    int mBase = blockIdx.x * 128;
    int wm = (wid & 1) * 64;
    int wn = (wid >> 1) * 32;

    float acc[4][4][4];
#pragma unroll
    for (int i = 0; i < 4; i++)
#pragma unroll
        for (int j = 0; j < 4; j++)
#pragma unroll
            for (int k = 0; k < 4; k++) acc[i][j][k] = 0.f;

    unsigned a_lof = (unsigned)((lane & 15) * ASTR + (lane >> 4) * 16);
    int l2 = lane & 15;
    unsigned w_lof = (unsigned)((l2 & 7) * ASTR + (l2 >> 3) * 16);

    auto load_stage = [&](int s, int k0) {
        unsigned stg = sb + s * STG_SZ;
        {
            int row = t >> 2, ch = t & 3;
            size_t go = (size_t)(mBase + row) * DW + k0 + ch * 8;
            unsigned d = stg + STG_AH + row * ASTR + ch * 16;
            cp_async16(d, Ah + go);
            cp_async16(d + (STG_AL - STG_AH), Al + go);
        }
#pragma unroll
        for (int r2 = 0; r2 < 2; r2++) {
            int i = t + r2 * 512;
            int row = i >> 2, ch = i & 3;
            size_t go = (size_t)row * DW + k0 + ch * 8;
            unsigned d = stg + STG_WH + row * ASTR + ch * 16;
            cp_async16(d, Wh + go);
            cp_async16(d + (STG_WL - STG_WH), Wl + go);
        }
    };

    load_stage(0, 0);
    CP_COMMIT();

    for (int c = 0; c < NCH; c++) {
        if (c + 1 < NCH) {
            load_stage((c + 1) & 1, (c + 1) * BK);
            CP_COMMIT();
            CP_WAIT(1);
        } else {
            CP_WAIT(0);
        }
        __syncthreads();

        unsigned stg = sb + (c & 1) * STG_SZ;
        unsigned aH = stg + STG_AH + wm * ASTR + a_lof;
        unsigned aL = stg + STG_AL + wm * ASTR + a_lof;
        unsigned wH = stg + STG_WH + wn * ASTR + w_lof;
        unsigned wL = stg + STG_WL + wn * ASTR + w_lof;

#pragma unroll
        for (int ks = 0; ks < 2; ks++) {
            unsigned kb = ks * 32;
            unsigned a[4][4], bh[4][2], bl[4][2];
#pragma unroll
            for (int mt = 0; mt < 4; mt++) ldsm_x4(a[mt], aH + mt * (16 * ASTR) + kb);
#pragma unroll
            for (int nt = 0; nt < 4; nt++) {
                ldsm_x2(bh[nt], wH + nt * (8 * ASTR) + kb);
                ldsm_x2(bl[nt], wL + nt * (8 * ASTR) + kb);
            }
#pragma unroll
            for (int mt = 0; mt < 4; mt++)
#pragma unroll
                for (int nt = 0; nt < 4; nt++) mma16816(acc[mt][nt], a[mt], bh[nt]);
#pragma unroll
            for (int mt = 0; mt < 4; mt++)
#pragma unroll
                for (int nt = 0; nt < 4; nt++) mma16816(acc[mt][nt], a[mt], bl[nt]);
#pragma unroll
            for (int mt = 0; mt < 4; mt++) ldsm_x4(a[mt], aL + mt * (16 * ASTR) + kb);
#pragma unroll
            for (int mt = 0; mt < 4; mt++)
#pragma unroll
                for (int nt = 0; nt < 4; nt++) mma16816(acc[mt][nt], a[mt], bh[nt]);
        }
        __syncthreads();
    }

    int gid = lane >> 2, tig = lane & 3;
#pragma unroll
    for (int nt = 0; nt < 4; nt++) {
        int col = wn + nt * 8 + tig * 2;
        float2 bv = *(const float2*)(bias + col);
#pragma unroll
        for (int mt = 0; mt < 4; mt++) {
            int r0 = mBase + wm + mt * 16 + gid;
            int r1 = r0 + 8;
            float x0 = (r0 < VV) ? acc[mt][nt][0] + bv.x : 0.f;
            float x1 = (r0 < VV) ? acc[mt][nt][1] + bv.y : 0.f;
            float x2 = (r1 < VV) ? acc[mt][nt][2] + bv.x : 0.f;
            float x3 = (r1 < VV) ? acc[mt][nt][3] + bv.y : 0.f;
            __nv_bfloat16 h0 = __float2bfloat16(x0), h1 = __float2bfloat16(x1);
            __nv_bfloat16 h2 = __float2bfloat16(x2), h3 = __float2bfloat16(x3);
            *(unsigned*)(outH + (size_t)r0 * DM + col) = pack_bf16(x0, x1);
            *(unsigned*)(outL + (size_t)r0 * DM + col) =
                pack_bf16(x0 - __bfloat162float(h0), x1 - __bfloat162float(h1));
            *(unsigned*)(outH + (size_t)r1 * DM + col) = pack_bf16(x2, x3);
            *(unsigned*)(outL + (size_t)r1 * DM + col) =
                pack_bf16(x2 - __bfloat162float(h2), x3 - __bfloat162float(h3));
        }
    }
}

// ============================================================
// split-K fp32 SGEMM (Q / O projections): partials to g_sg[z]
// grid (M/64, N/64, 4); each z covers K/4.
// ============================================================
__global__ __launch_bounds__(256) void sgemm64s(
    const float* __restrict__ A, const float* __restrict__ Bw,
    float* __restrict__ Cp, int M, int N, int K)
{
    __shared__ float As[16][68];
    __shared__ float Bs[16][68];
    int t = threadIdx.x, tx = t & 15, ty = t >> 4;
    int mB = blockIdx.x * 64, nB = blockIdx.y * 64;
    int kc = K / 4;
    int kBeg = blockIdx.z * kc, kEnd = kBeg + kc;
    float acc[4][4];
#pragma unroll
    for (int i = 0; i < 4; i++)
#pragma unroll
        for (int j = 0; j < 4; j++) acc[i][j] = 0.f;

    for (int k0 = kBeg; k0 < kEnd; k0 += 16) {
        {
            int row = t >> 2, kk = (t & 3) * 4;
            float4 av = *(const float4*)(A + (size_t)(mB + row) * K + k0 + kk);
            As[kk + 0][row] = av.x; As[kk + 1][row] = av.y;
            As[kk + 2][row] = av.z; As[kk + 3][row] = av.w;
        }
        {
            int kr = t >> 4, c4 = (t & 15) * 4;
            *(float4*)&Bs[kr][c4] = *(const float4*)(Bw + (size_t)(k0 + kr) * N + nB + c4);
        }
        __syncthreads();
#pragma unroll
        for (int kk = 0; kk < 16; kk++) {
            float4 a = *(const float4*)&As[kk][ty * 4];
            float4 b = *(const float4*)&Bs[kk][tx * 4];
            float am[4] = {a.x, a.y, a.z, a.w};
            float bn[4] = {b.x, b.y, b.z, b.w};
#pragma unroll
            for (int i = 0; i < 4; i++)
#pragma unroll
                for (int j = 0; j < 4; j++) acc[i][j] += am[i] * bn[j];
        }
        __syncthreads();
    }
    float* outz = Cp + (size_t)blockIdx.z * M * N;
#pragma unroll
    for (int i = 0; i < 4; i++) {
        int m = mB + ty * 4 + i;
#pragma unroll
        for (int j = 0; j < 4; j++) {
            int n = nB + tx * 4 + j;
            outz[(size_t)m * N + n] = acc[i][j];
        }
    }
}

__global__ void combine_bias(const float* __restrict__ Cp, const float* __restrict__ bias,
                             float* __restrict__ out)
{
    int i = blockIdx.x * blockDim.x + threadIdx.x;
    const int MN = BB * LL * DM;
    if (i >= MN) return;
    out[i] = Cp[i] + Cp[MN + i] + Cp[2 * MN + i] + Cp[3 * MN + i] + bias[i & (DM - 1)];
}

// ============================================================
// Tensor-core fused attention v2: S' = Q K^T orientation.
// 16 warps, warp tile 32l x 32v. P stays in registers (C-frag -> A-frag).
// Softmax over l = column reduction (shfl + smem red).
// ============================================================
#define KSTR 80
#define OFF_QH 0
#define OFF_QL 10240
#define OFF_KV 20480
#define KVBUF 40960         /* KH 0, KL 10240, VH 20480, VL 30720 */
#define OFF_RED (OFF_KV + 2 * KVBUF)        /* 102400 */
#define OFF_RN  (OFF_RED + 2048)            /* 104448 */
#define ATTN_SMEM (OFF_RN + 512)            /* 104960 */

__global__ void __launch_bounds__(512, 1)
attn_tc(const __nv_bfloat16* __restrict__ Qh, const __nv_bfloat16* __restrict__ Ql,
        const __nv_bfloat16* __restrict__ Kh, const __nv_bfloat16* __restrict__ Kl,
        const __nv_bfloat16* __restrict__ Vh, const __nv_bfloat16* __restrict__ Vl,
        float* __restrict__ part)
{
    extern __shared__ char smem[];
    unsigned sb = smem_u32(smem);
    float* red = (float*)(smem + OFF_RED);   // [128 v][4 lg]
    float* rn  = (float*)(smem + OFF_RN);    // [128 v]

    int t = threadIdx.x, lane = t & 31, wid = t >> 5;
    int s = blockIdx.x, h = blockIdx.y, b = blockIdx.z;
    int gid = lane >> 2, tig = lane & 3;
    int lg = wid & 3, vg = wid >> 2;
    int wl = lg * 32, wv = vg * 32;

    // ---- load Q slice [128 l][32 e] hi/lo ----
    {
        size_t qbase = (size_t)(b * LL) * DM + h * EE;
        int row = t >> 2, c = t & 3;
        size_t go = qbase + (size_t)row * DM + c * 8;
        unsigned d = sb + row * KSTR + c * 16;
        cp_async16(d + OFF_QH, Qh + go);
        cp_async16(d + OFF_QL, Ql + go);
    }
    CP_COMMIT();
    CP_WAIT(0);
    __syncthreads();

    // ---- Q A-fragments (m = warp's 32 l rows, k = 32 e) ----
    unsigned qhf[2][2][4], qlf[2][2][4];
    {
        unsigned alof = (unsigned)((lane & 15) * KSTR + (lane >> 4) * 16);
#pragma unroll
        for (int mt = 0; mt < 2; mt++)
#pragma unroll
            for (int k = 0; k < 2; k++) {
                unsigned off = (wl + 16 * mt) * KSTR + alof + k * 32;
                ldsm_x4(qhf[mt][k], sb + OFF_QH + off);
                ldsm_x4(qlf[mt][k], sb + OFF_QL + off);
            }
    }

    float accO[2][4][4];
#pragma unroll
    for (int i = 0; i < 2; i++)
#pragma unroll
        for (int j = 0; j < 4; j++)
#pragma unroll
            for (int q = 0; q < 4; q++) accO[i][j][q] = 0.f;

    size_t hof = (size_t)h * EE;
    auto load_kv = [&](int buf, int v0) {
        unsigned base = sb + OFF_KV + buf * KVBUF;
        int row = t >> 2, c = t & 3;
        size_t go = (size_t)(v0 + row) * DM + hof + c * 8;
        unsigned d = base + row * KSTR + c * 16;
        cp_async16(d,         Kh + go);
        cp_async16(d + 10240, Kl + go);
        cp_async16(d + 20480, Vh + go);
        cp_async16(d + 30720, Vl + go);
    };

    load_kv(0, s * 128);
    CP_COMMIT();

    const float CC = 0.25503327723425473f;  // (1/sqrt(32)) * log2(e)
    int l2 = lane & 15;
    unsigned kb_lof = (unsigned)((l2 & 7) * KSTR + (l2 >> 3) * 16);

    int it = 0;
    for (int tile = s; tile < NTILE; tile += SPLITS, it++) {
        CP_WAIT(0);
        __syncthreads();   // buffer ready; all warps done with prev iter (KV recycle + red reuse safe)

        int nxt = tile + SPLITS;
        if (nxt < NTILE) {
            load_kv((it + 1) & 1, nxt * 128);
            CP_COMMIT();
        }
        unsigned kvb = sb + OFF_KV + (it & 1) * KVBUF;

        // ---- S' GEMM: accS[2 mt][4 n][4], n over warp's 32 v-cols ----
        float accS[2][4][4];
#pragma unroll
        for (int mt = 0; mt < 2; mt++)
#pragma unroll
            for (int n = 0; n < 4; n++)
#pragma unroll
                for (int q = 0; q < 4; q++) accS[mt][n][q] = 0.f;

#pragma unroll
        for (int k = 0; k < 2; k++) {
            unsigned kbh[4][2], kbl[4][2];
#pragma unroll
            for (int n = 0; n < 4; n++) {
                unsigned addr = kvb + (wv + n * 8) * KSTR + kb_lof + k * 32;
                ldsm_x2(kbh[n], addr);
                ldsm_x2(kbl[n], addr + 10240);
            }
#pragma unroll
            for (int mt = 0; mt < 2; mt++)
#pragma unroll
                for (int n = 0; n < 4; n++) {
                    mma16816(accS[mt][n], qhf[mt][k], kbh[n]);
                    mma16816(accS[mt][n], qlf[mt][k], kbh[n]);
                    mma16816(accS[mt][n], qhf[mt][k], kbl[n]);
                }
        }

        // ---- exp + per-warp column sums (softmax over l = columns... rows l) ----
        float s0[4], s1[4];
#pragma unroll
        for (int n = 0; n < 4; n++) { s0[n] = 0.f; s1[n] = 0.f; }
#pragma unroll
        for (int mt = 0; mt < 2; mt++)
#pragma unroll
            for (int n = 0; n < 4; n++) {
                accS[mt][n][0] = ex2(accS[mt][n][0] * CC);
                accS[mt][n][1] = ex2(accS[mt][n][1] * CC);
                accS[mt][n][2] = ex2(accS[mt][n][2] * CC);
                accS[mt][n][3] = ex2(accS[mt][n][3] * CC);
                s0[n] += accS[mt][n][0] + accS[mt][n][2];
                s1[n] += accS[mt][n][1] + accS[mt][n][3];
            }
#pragma unroll
        for (int n = 0; n < 4; n++) {
#pragma unroll
            for (int ofs = 4; ofs < 32; ofs <<= 1) {
                s0[n] += __shfl_xor_sync(0xffffffffu, s0[n], ofs);
                s1[n] += __shfl_xor_sync(0xffffffffu, s1[n], ofs);
            }
        }
        if (gid == 0) {
#pragma unroll
            for (int n = 0; n < 4; n++) {
                red[(wv + n * 8 + tig * 2) * 4 + lg] = s0[n];
                red[(wv + n * 8 + tig * 2 + 1) * 4 + lg] = s1[n];
            }
        }
        __syncthreads();
        if (t < 128) {
            float v = red[t * 4] + red[t * 4 + 1] + red[t * 4 + 2] + red[t * 4 + 3];
            rn[t] = 1.f / v;
        }
        __syncthreads();

        // ---- normalize accS in place ----
#pragma unroll
        for (int n = 0; n < 4; n++) {
            float r0 = rn[wv + n * 8 + tig * 2];
            float r1 = rn[wv + n * 8 + tig * 2 + 1];
#pragma unroll
            for (int mt = 0; mt < 2; mt++) {
                accS[mt][n][0] *= r0;
                accS[mt][n][1] *= r1;
                accS[mt][n][2] *= r0;
                accS[mt][n][3] *= r1;
            }
        }

        // ---- O GEMM: accO += P (regs, hi/lo) @ V ----
#pragma unroll
        for (int ks = 0; ks < 2; ks++) {
            unsigned vbh[4][2], vbl[4][2];
#pragma unroll
            for (int ne = 0; ne < 4; ne++) {
                unsigned addr = kvb + 20480 + (wv + ks * 16 + l2) * KSTR + ne * 16;
                ldsm_x2_t(vbh[ne], addr);
                ldsm_x2_t(vbl[ne], addr + 10240);
            }
#pragma unroll
            for (int mt = 0; mt < 2; mt++) {
                // pack P C-frags (tiles 2ks, 2ks+1) into m16k16 A-frags hi/lo
                float p0 = accS[mt][2 * ks][0], p1 = accS[mt][2 * ks][1];
                float p2 = accS[mt][2 * ks][2], p3 = accS[mt][2 * ks][3];
                float p4 = accS[mt][2 * ks + 1][0], p5 = accS[mt][2 * ks + 1][1];
                float p6 = accS[mt][2 * ks + 1][2], p7 = accS[mt][2 * ks + 1][3];
                unsigned aph[4], apl[4];
                aph[0] = pack_bf16(p0, p1);
                aph[1] = pack_bf16(p2, p3);
                aph[2] = pack_bf16(p4, p5);
                aph[3] = pack_bf16(p6, p7);
                apl[0] = pack_bf16(p0 - __bfloat162float(__float2bfloat16(p0)),
                                   p1 - __bfloat162float(__float2bfloat16(p1)));
                apl[1] = pack_bf16(p2 - __bfloat162float(__float2bfloat16(p2)),
                                   p3 - __bfloat162float(__float2bfloat16(p3)));
                apl[2] = pack_bf16(p4 - __bfloat162float(__float2bfloat16(p4)),
                                   p5 - __bfloat162float(__float2bfloat16(p5)));
                apl[3] = pack_bf16(p6 - __bfloat162float(__float2bfloat16(p6)),
                                   p7 - __bfloat162float(__float2bfloat16(p7)));
#pragma unroll
                for (int ne = 0; ne < 4; ne++) {
                    mma16816(accO[mt][ne], aph, vbh[ne]);
                    mma16816(accO[mt][ne], aph, vbl[ne]);
                    mma16816(accO[mt][ne], apl, vbh[ne]);
                }
            }
        }
    }

    // ---- write split partials (slot per (s, vg)) ----
    float* pout = part + (size_t)(((b * HH + h) * SPLITS + s) * 4 + vg) * LL * EE;
#pragma unroll
    for (int mt = 0; mt < 2; mt++) {
        int l = wl + mt * 16 + gid;
#pragma unroll
        for (int ne = 0; ne < 4; ne++) {
            int e = ne * 8 + tig * 2;
            *(float2*)(pout + l * EE + e) = make_float2(accO[mt][ne][0], accO[mt][ne][1]);
            *(float2*)(pout + (l + 8) * EE + e) = make_float2(accO[mt][ne][2], accO[mt][ne][3]);
        }
    }
}

__global__ void reduce_part(const float* __restrict__ part, float* __restrict__ reprog)
{
    int t = blockIdx.x * blockDim.x + threadIdx.x;
    if (t >= BB * LL * DM) return;
    int e = t & 31;
    int h = (t >> 5) & 7;
    int l = (t >> 8) & 127;
    int b = t >> 15;
    const float* p = part + (size_t)(b * HH + h) * SPL4 * LL * EE + l * EE + e;
    float acc = 0.f;
#pragma unroll
    for (int s2 = 0; s2 < SPL4; s2++) acc += p[(size_t)s2 * LL * EE];
    reprog[t] = acc;
}

// ============================================================
// Launch
// ============================================================
extern "C" void kernel_launch(void* const* d_in, const int* in_sizes, int n_in,
                              void* d_out, int out_size)
{
    (void)in_sizes; (void)n_in; (void)out_size;
    const float* ts = (const float*)d_in[0];
    const float* we = (const float*)d_in[1];
    const float* Wq = (const float*)d_in[2];
    const float* bq = (const float*)d_in[3];
    const float* Wk = (const float*)d_in[4];
    const float* bk = (const float*)d_in[5];
    const float* Wv = (const float*)d_in[6];
    const float* bv = (const float*)d_in[7];
    const float* Wo = (const float*)d_in[8];
    const float* bo = (const float*)d_in[9];
    float* out = (float*)d_out;

    float *gq, *gp, *gr, *gsg;
    __nv_bfloat16 *ah, *al, *wkh, *wkl, *wvh, *wvl, *kh, *kl, *vh, *vl, *qh, *ql;
    cudaGetSymbolAddress((void**)&gq, g_query);
    cudaGetSymbolAddress((void**)&gp, g_part);
    cudaGetSymbolAddress((void**)&gr, g_reprog);
    cudaGetSymbolAddress((void**)&gsg, g_sg);
    cudaGetSymbolAddress((void**)&ah, g_Ah);
    cudaGetSymbolAddress((void**)&al, g_Al);
    cudaGetSymbolAddress((void**)&wkh, g_Wkh);
    cudaGetSymbolAddress((void**)&wkl, g_Wkl);
    cudaGetSymbolAddress((void**)&wvh, g_Wvh);
    cudaGetSymbolAddress((void**)&wvl, g_Wvl);
    cudaGetSymbolAddress((void**)&kh, g_Kh);
    cudaGetSymbolAddress((void**)&kl, g_Kl);
    cudaGetSymbolAddress((void**)&vh, g_Vh);
    cudaGetSymbolAddress((void**)&vl, g_Vl);
    cudaGetSymbolAddress((void**)&qh, g_Qh);
    cudaGetSymbolAddress((void**)&ql, g_Ql);

    cudaFuncSetAttribute(kv_gemm, cudaFuncAttributeMaxDynamicSharedMemorySize, KV_SMEM);
    cudaFuncSetAttribute(attn_tc, cudaFuncAttributeMaxDynamicSharedMemorySize, ATTN_SMEM);

    // conversions
    {
        size_t tot4 = (size_t)VPAD * DW / 4;
        conv_a<<<(unsigned)((tot4 + 255) / 256), 256>>>(we, ah, al);
        dim3 wb(32, 8);
        conv_w<<<dim3(DW / 32, DM / 32), wb>>>(Wk, wkh, wkl);
        conv_w<<<dim3(DW / 32, DM / 32), wb>>>(Wv, wvh, wvl);
    }
    // Q projection (split-K) + bf16 split
    sgemm64s<<<dim3(BB * LL / 64, DM / 64, 4), 256>>>(ts, Wq, gsg, BB * LL, DM, DM);
    combine_bias<<<(BB * LL * DM + 255) / 256, 256>>>(gsg, bq, gq);
    conv_q<<<(BB * LL * DM + 255) / 256, 256>>>(gq, qh, ql);
    // K / V projections -> bf16 hi/lo
    kv_gemm<<<VPAD / 128, 512, KV_SMEM>>>(ah, al, wkh, wkl, bk, kh, kl);
    kv_gemm<<<VPAD / 128, 512, KV_SMEM>>>(ah, al, wvh, wvl, bv, vh, vl);
    // tensor-core attention
    attn_tc<<<dim3(SPLITS, HH, BB), 512, ATTN_SMEM>>>(qh, ql, kh, kl, vh, vl, gp);
    reduce_part<<<(BB * LL * DM + 255) / 256, 256>>>(gp, gr);
    // output projection (split-K)
    sgemm64s<<<dim3(BB * LL / 64, DM / 64, 4), 256>>>(gr, Wo, gsg, BB * LL, DM, DM);
    combine_bias<<<(BB * LL * DM + 255) / 256, 256>>>(gsg, bo, out);
}